// round 13
// baseline (speedup 1.0000x reference)
#include <cuda_runtime.h>
#include <cuda_bf16.h>
#include <math.h>
#include <stdint.h>

#define B_     32
#define S_     512
#define DM     512
#define NH     8
#define NL     4
#define DFF    2048
#define FEAT   2048
#define NTOK   (B_ * S_)

// ---------------- scratch ----------------
__device__ float g_h   [NTOK * DM];
__device__ float g_q   [NTOK * DM];   // reused: qh/ql bf16
__device__ float g_k   [NTOK * DM];   // reused: kh/kl bf16
__device__ float g_v   [NTOK * DM];   // reused: vh/vl bf16
__device__ float g_tmp [NTOK * DM];
__device__ float g_pool[B_ * DM];
__device__ float g_bqkv[NL * 1536];

__device__ __nv_bfloat16 g_xh[NTOK * FEAT];
__device__ __nv_bfloat16 g_xl[NTOK * FEAT];
__device__ __nv_bfloat16 g_hh[NTOK * DM];
__device__ __nv_bfloat16 g_hl[NTOK * DM];
__device__ __nv_bfloat16 g_ch[NTOK * DM];
__device__ __nv_bfloat16 g_cl[NTOK * DM];
#define WTOT 13631488
__device__ __nv_bfloat16 g_wth[WTOT];
__device__ __nv_bfloat16 g_wtl[WTOT];

#define LBASE   1048576
#define LSTRIDE 3145728

// ---------------- helpers ----------------
__device__ __forceinline__ uint32_t smem_u32(const void* p) {
    uint32_t a;
    asm("{ .reg .u64 t; cvta.to.shared.u64 t, %1; cvt.u32.u64 %0, t; }" : "=r"(a) : "l"(p));
    return a;
}
__device__ __forceinline__ void cp16(uint32_t s, const void* g) {
    asm volatile("cp.async.cg.shared.global [%0], [%1], 16;" :: "r"(s), "l"(g));
}
#define CP_COMMIT() asm volatile("cp.async.commit_group;" ::: "memory")

__device__ __forceinline__ void ldm4(uint32_t* r, uint32_t addr) {
    asm volatile("ldmatrix.sync.aligned.m8n8.x4.shared.b16 {%0,%1,%2,%3}, [%4];"
                 : "=r"(r[0]), "=r"(r[1]), "=r"(r[2]), "=r"(r[3]) : "r"(addr));
}
__device__ __forceinline__ void ldm4t(uint32_t* r, uint32_t addr) {
    asm volatile("ldmatrix.sync.aligned.m8n8.x4.trans.shared.b16 {%0,%1,%2,%3}, [%4];"
                 : "=r"(r[0]), "=r"(r[1]), "=r"(r[2]), "=r"(r[3]) : "r"(addr));
}
__device__ __forceinline__ void mma16816(float* c, const uint32_t* a, const uint32_t* b) {
    asm volatile(
        "mma.sync.aligned.m16n8k16.row.col.f32.bf16.bf16.f32 "
        "{%0,%1,%2,%3}, {%4,%5,%6,%7}, {%8,%9}, {%0,%1,%2,%3};"
        : "+f"(c[0]), "+f"(c[1]), "+f"(c[2]), "+f"(c[3])
        : "r"(a[0]), "r"(a[1]), "r"(a[2]), "r"(a[3]), "r"(b[0]), "r"(b[1]));
}
__device__ __forceinline__ void split2(float a, float b, uint32_t& hi, uint32_t& lo) {
    __nv_bfloat162 h = __floats2bfloat162_rn(a, b);
    __nv_bfloat162 l = __floats2bfloat162_rn(a - __bfloat162float(h.x),
                                             b - __bfloat162float(h.y));
    hi = *(uint32_t*)&h;
    lo = *(uint32_t*)&l;
}

// ---------------------------------------------------------------------------
// Split-bf16 HMMA GEMM: C[M,N] = A[M,K] @ Bt[N,K]^T (+bias, epilogues)
// BM=128, BN=256, BK=32, 256 thr (8 warps of 64x64), 4-stage cp.async,
// 1 CTA/SM. Warp tile 64x64 cuts LDSM traffic to 85 B/MMA (was 128).
// EPI: 0 bias, 1 +relu, 2 +posenc, 3 +residual, 4 QKV-routed split output.
// Stage layout: Ah 0 | Al 8K | Bh 16K | Bl 32K  (48KB/stage)
// ---------------------------------------------------------------------------
#define GSTAGE 49152
#define GSMEM_TOTAL (4 * GSTAGE)

template<int EPI, bool WSPLIT, bool WF32>
__global__ __launch_bounds__(256, 1)
void gemm_mma(const __nv_bfloat16* __restrict__ Ah, const __nv_bfloat16* __restrict__ Al,
              const __nv_bfloat16* __restrict__ Bh, const __nv_bfloat16* __restrict__ Bl,
              const float* __restrict__ bias, const float* __restrict__ res,
              float* __restrict__ Cf, __nv_bfloat16* __restrict__ Ch,
              __nv_bfloat16* __restrict__ Cl,
              __nv_bfloat16* __restrict__ Ch2, __nv_bfloat16* __restrict__ Cl2,
              __nv_bfloat16* __restrict__ Ch3, __nv_bfloat16* __restrict__ Cl3,
              int N, int K)
{
    extern __shared__ char smem[];
    const uint32_t sb = smem_u32(smem);
    const int t = threadIdx.x, lane = t & 31, wid = t >> 5;
    const int wm = wid & 1, wn = wid >> 1;           // 2m x 4n warps
    const int m0 = blockIdx.y << 7, n0 = blockIdx.x << 8;

    // loader: A rows t>>1 (2 thr/row, 2 chunks each); B row t (4 chunks)
    const int lrA = t >> 1, lcA = (t & 1) * 2;
    const int lswA = (lrA & 6) >> 1;
    const int lswB = (t & 6) >> 1;
    const char* gA_h = (const char*)(Ah + (size_t)(m0 + lrA) * K);
    const char* gA_l = (const char*)(Al + (size_t)(m0 + lrA) * K);
    const char* gB_h = (const char*)(Bh + (size_t)(n0 + t) * K);
    const char* gB_l = (const char*)(Bl + (size_t)(n0 + t) * K);

    auto load_stage = [&](int buf, int k0) {
        uint32_t base = sb + buf * GSTAGE;
#pragma unroll
        for (int c = lcA; c < lcA + 2; c++) {
            uint32_t so = (uint32_t)(lrA * 64 + ((c ^ lswA) << 4));
            size_t go = (size_t)(k0 + c * 8) * 2;
            cp16(base + so,        gA_h + go);
            cp16(base + 8192 + so, gA_l + go);
        }
#pragma unroll
        for (int c = 0; c < 4; c++) {
            uint32_t so = (uint32_t)(t * 64 + ((c ^ lswB) << 4));
            size_t go = (size_t)(k0 + c * 8) * 2;
            cp16(base + 16384 + so, gB_h + go);
            cp16(base + 32768 + so, gB_l + go);
        }
        CP_COMMIT();
    };

    const int csa = (lane >> 4) & 1;
    const int csb = (lane >> 3) & 1;
    uint32_t offA[4], sA[4];
#pragma unroll
    for (int mi = 0; mi < 4; mi++) {
        int r = wm * 64 + mi * 16 + (lane & 15);
        offA[mi] = r * 64;
        sA[mi] = (r & 6) >> 1;
    }
    uint32_t offB[4], sB[4];
#pragma unroll
    for (int g = 0; g < 4; g++) {
        int r = wn * 64 + g * 16 + (lane & 7) + ((lane & 16) >> 1);
        offB[g] = r * 64;
        sB[g] = (r & 6) >> 1;
    }

    float acc[4][8][4];
#pragma unroll
    for (int i = 0; i < 4; i++)
#pragma unroll
        for (int j = 0; j < 8; j++)
#pragma unroll
            for (int e = 0; e < 4; e++) acc[i][j][e] = 0.0f;

    const int nst = K >> 5;
    load_stage(0, 0);
    load_stage(1, 32);
    load_stage(2, 64);

    for (int st = 0; st < nst; st++) {
        int rem = nst - 1 - st;
        if (rem >= 2)      asm volatile("cp.async.wait_group 2;" ::: "memory");
        else if (rem == 1) asm volatile("cp.async.wait_group 1;" ::: "memory");
        else               asm volatile("cp.async.wait_group 0;" ::: "memory");
        __syncthreads();
        if (st + 3 < nst) load_stage((st + 3) & 3, (st + 3) * 32);

        uint32_t base = sb + (st & 3) * GSTAGE;
#pragma unroll
        for (int ks = 0; ks < 2; ks++) {
            uint32_t ah[4][4], al[4][4];
#pragma unroll
            for (int mi = 0; mi < 4; mi++) {
                uint32_t ca = (((2 * ks + csa) ^ sA[mi]) << 4);
                ldm4(ah[mi], base + offA[mi] + ca);
                ldm4(al[mi], base + 8192 + offA[mi] + ca);
            }
#pragma unroll
            for (int g = 0; g < 4; g++) {
                uint32_t cb = (((2 * ks + csb) ^ sB[g]) << 4);
                uint32_t rh[4], rl[4];
                ldm4(rh, base + 16384 + offB[g] + cb);
                ldm4(rl, base + 32768 + offB[g] + cb);
#pragma unroll
                for (int mi = 0; mi < 4; mi++) {
                    mma16816(acc[mi][2*g],   ah[mi], &rh[0]);
                    mma16816(acc[mi][2*g+1], ah[mi], &rh[2]);
                }
#pragma unroll
                for (int mi = 0; mi < 4; mi++) {
                    mma16816(acc[mi][2*g],   ah[mi], &rl[0]);
                    mma16816(acc[mi][2*g+1], ah[mi], &rl[2]);
                }
#pragma unroll
                for (int mi = 0; mi < 4; mi++) {
                    mma16816(acc[mi][2*g],   al[mi], &rh[0]);
                    mma16816(acc[mi][2*g+1], al[mi], &rh[2]);
                }
            }
        }
    }

    // ---- epilogue ----
    const float kPE = (float)(-9.210340371976184 / 512.0);
    const int rbase = m0 + wm * 64 + (lane >> 2);
    const int cbase = n0 + wn * 64 + (lane & 3) * 2;
    __nv_bfloat16 *Oh = Ch, *Ol = Cl;
    if (EPI == 4) {
        const int sel = n0 >> 9;
        Oh = (sel == 0) ? Ch : (sel == 1) ? Ch2 : Ch3;
        Ol = (sel == 0) ? Cl : (sel == 1) ? Cl2 : Cl3;
    }
#pragma unroll
    for (int mi = 0; mi < 4; mi++) {
#pragma unroll
        for (int half = 0; half < 2; half++) {
            const int row = rbase + mi * 16 + half * 8;
            const int s = row & (S_ - 1);
#pragma unroll
            for (int ni = 0; ni < 8; ni++) {
                const int col = cbase + ni * 8;
                const int ocol = (EPI == 4) ? (col & 511) : col;
                float vx = acc[mi][ni][2 * half + 0];
                float vy = acc[mi][ni][2 * half + 1];
                float2 bb = *(const float2*)(bias + col);
                vx += bb.x; vy += bb.y;
                if (EPI == 1) { vx = fmaxf(vx, 0.0f); vy = fmaxf(vy, 0.0f); }
                if (EPI == 2) {
                    float a = (float)s * expf((float)col * kPE);
                    vx += sinf(a); vy += cosf(a);
                }
                if (EPI == 3) {
                    float2 rr = *(const float2*)(res + (size_t)row * N + col);
                    vx += rr.x; vy += rr.y;
                }
                if (WF32)
                    *(float2*)(Cf + (size_t)row * N + ocol) = make_float2(vx, vy);
                if (WSPLIT) {
                    uint32_t hw, lw;
                    split2(vx, vy, hw, lw);
                    *(uint32_t*)(Oh + (size_t)row * N + ocol) = hw;
                    *(uint32_t*)(Ol + (size_t)row * N + ocol) = lw;
                }
            }
        }
    }
}

// ---------------------------------------------------------------------------
// Split-bf16 HMMA flash attention, K/V double-buffered.
// Smem: Qh Ql | buf0{Kh Kl Vh Vl} | buf1{Kh Kl Vh Vl} = 10 tiles.
// ---------------------------------------------------------------------------
#define AST 72
#define ATILE (64 * AST)
#define ATTN_SMEM (10 * ATILE * 2)   // 92160 B

__global__ __launch_bounds__(128)
void attn_mma(const __nv_bfloat16* __restrict__ qh, const __nv_bfloat16* __restrict__ ql,
              const __nv_bfloat16* __restrict__ kh, const __nv_bfloat16* __restrict__ kl,
              const __nv_bfloat16* __restrict__ vh, const __nv_bfloat16* __restrict__ vl,
              __nv_bfloat16* __restrict__ ch, __nv_bfloat16* __restrict__ cl)
{
    extern __shared__ __nv_bfloat16 smb[];
    const uint32_t sq = smem_u32(smb);
    const int t = threadIdx.x, lane = t & 31, w = t >> 5;
    const int b = blockIdx.y >> 3, h = blockIdx.y & 7;
    const int hoff = h << 6;
    const size_t btok0 = (size_t)b * S_;
    const size_t qtok0 = btok0 + ((size_t)blockIdx.x << 6);

    const int lr = t >> 1, lc0 = (t & 1) * 4;

    auto load_kv = [&](int buf, int kt) {
        uint32_t kb = (2 + 4 * buf) * ATILE;
        size_t tok = btok0 + kt * 64 + lr;
        const __nv_bfloat16* gk_h = kh + tok * DM + hoff;
        const __nv_bfloat16* gk_l = kl + tok * DM + hoff;
        const __nv_bfloat16* gv_h = vh + tok * DM + hoff;
        const __nv_bfloat16* gv_l = vl + tok * DM + hoff;
#pragma unroll
        for (int c = lc0; c < lc0 + 4; c++) {
            cp16(sq + (kb             + lr * AST + c * 8) * 2, gk_h + c * 8);
            cp16(sq + (kb + ATILE     + lr * AST + c * 8) * 2, gk_l + c * 8);
            cp16(sq + (kb + 2 * ATILE + lr * AST + c * 8) * 2, gv_h + c * 8);
            cp16(sq + (kb + 3 * ATILE + lr * AST + c * 8) * 2, gv_l + c * 8);
        }
        CP_COMMIT();
    };

    // Q (group 1) + KV0 (group 2)
    {
        const __nv_bfloat16* gq_h = qh + (qtok0 + lr) * DM + hoff;
        const __nv_bfloat16* gq_l = ql + (qtok0 + lr) * DM + hoff;
#pragma unroll
        for (int c = lc0; c < lc0 + 4; c++) {
            cp16(sq + (lr * AST + c * 8) * 2,           gq_h + c * 8);
            cp16(sq + (ATILE + lr * AST + c * 8) * 2,   gq_l + c * 8);
        }
        CP_COMMIT();
    }
    load_kv(0, 0);

    float m1 = -INFINITY, m2 = -INFINITY, l1 = 0.0f, l2 = 0.0f;
    float o[8][4];
#pragma unroll
    for (int j = 0; j < 8; j++)
#pragma unroll
        for (int e = 0; e < 4; e++) o[j][e] = 0.0f;

    const uint32_t a_off = ((16 * w + (lane & 15)) * AST + ((lane >> 4) << 3)) * 2;
    const uint32_t k_row = (lane & 7) + ((lane & 16) >> 1);
    const uint32_t k_col = (((lane >> 3) & 1) << 3);
    const uint32_t v_off = ((lane & 15) * AST + ((lane >> 4) << 3)) * 2;

    for (int kt = 0; kt < 8; kt++) {
        const int buf = kt & 1;
        __syncthreads();                       // guard (kt-1)^1 buffer reuse
        if (kt + 1 < 8) {
            load_kv((kt + 1) & 1, kt + 1);
            asm volatile("cp.async.wait_group 1;" ::: "memory");
        } else {
            asm volatile("cp.async.wait_group 0;" ::: "memory");
        }
        __syncthreads();

        const uint32_t KH = (2 + 4 * buf) * ATILE;
        const uint32_t KL = KH + ATILE;
        const uint32_t VH = KH + 2 * ATILE;
        const uint32_t VL = KH + 3 * ATILE;

        float c_[8][4];
#pragma unroll
        for (int n = 0; n < 8; n++)
#pragma unroll
            for (int e = 0; e < 4; e++) c_[n][e] = 0.0f;

#pragma unroll
        for (int kc = 0; kc < 4; kc++) {
            uint32_t aqh[4], aql[4];
            ldm4(aqh, sq + a_off + kc * 32);
            ldm4(aql, sq + ATILE * 2 + a_off + kc * 32);
#pragma unroll
            for (int g = 0; g < 4; g++) {
                uint32_t rh[4], rl[4];
                uint32_t ko = ((g * 16 + k_row) * AST + kc * 16 + k_col) * 2;
                ldm4(rh, sq + KH * 2 + ko);
                ldm4(rl, sq + KL * 2 + ko);
                mma16816(c_[2*g],   aqh, &rh[0]);
                mma16816(c_[2*g+1], aqh, &rh[2]);
                mma16816(c_[2*g],   aqh, &rl[0]);
                mma16816(c_[2*g+1], aqh, &rl[2]);
                mma16816(c_[2*g],   aql, &rh[0]);
                mma16816(c_[2*g+1], aql, &rh[2]);
            }
        }

        float mx1 = -INFINITY, mx2 = -INFINITY;
#pragma unroll
        for (int n = 0; n < 8; n++) {
#pragma unroll
            for (int e = 0; e < 4; e++) c_[n][e] *= 0.125f;
            mx1 = fmaxf(mx1, fmaxf(c_[n][0], c_[n][1]));
            mx2 = fmaxf(mx2, fmaxf(c_[n][2], c_[n][3]));
        }
#pragma unroll
        for (int off = 1; off < 4; off <<= 1) {
            mx1 = fmaxf(mx1, __shfl_xor_sync(0xffffffffu, mx1, off));
            mx2 = fmaxf(mx2, __shfl_xor_sync(0xffffffffu, mx2, off));
        }
        float mn1 = fmaxf(m1, mx1), mn2 = fmaxf(m2, mx2);
        float corr1 = __expf(m1 - mn1), corr2 = __expf(m2 - mn2);
        m1 = mn1; m2 = mn2;
        float s1 = 0.0f, s2 = 0.0f;
#pragma unroll
        for (int n = 0; n < 8; n++) {
            c_[n][0] = __expf(c_[n][0] - mn1);
            c_[n][1] = __expf(c_[n][1] - mn1);
            c_[n][2] = __expf(c_[n][2] - mn2);
            c_[n][3] = __expf(c_[n][3] - mn2);
            s1 += c_[n][0] + c_[n][1];
            s2 += c_[n][2] + c_[n][3];
        }
#pragma unroll
        for (int off = 1; off < 4; off <<= 1) {
            s1 += __shfl_xor_sync(0xffffffffu, s1, off);
            s2 += __shfl_xor_sync(0xffffffffu, s2, off);
        }
        l1 = l1 * corr1 + s1;
        l2 = l2 * corr2 + s2;
#pragma unroll
        for (int j = 0; j < 8; j++) {
            o[j][0] *= corr1; o[j][1] *= corr1;
            o[j][2] *= corr2; o[j][3] *= corr2;
        }

#pragma unroll
        for (int kc = 0; kc < 4; kc++) {
            uint32_t ph[4], pl[4];
            split2(c_[2*kc][0],   c_[2*kc][1],   ph[0], pl[0]);
            split2(c_[2*kc][2],   c_[2*kc][3],   ph[1], pl[1]);
            split2(c_[2*kc+1][0], c_[2*kc+1][1], ph[2], pl[2]);
            split2(c_[2*kc+1][2], c_[2*kc+1][3], ph[3], pl[3]);
#pragma unroll
            for (int j = 0; j < 4; j++) {
                uint32_t rvh[4], rvl[4];
                uint32_t vo = (kc * 16 * AST + j * 16) * 2 + v_off;
                ldm4t(rvh, sq + VH * 2 + vo);
                ldm4t(rvl, sq + VL * 2 + vo);
                mma16816(o[2*j],   ph, &rvh[0]);
                mma16816(o[2*j+1], ph, &rvh[2]);
                mma16816(o[2*j],   ph, &rvl[0]);
                mma16816(o[2*j+1], ph, &rvl[2]);
                mma16816(o[2*j],   pl, &rvh[0]);
                mma16816(o[2*j+1], pl, &rvh[2]);
            }
        }
    }

    float inv1 = 1.0f / l1, inv2 = 1.0f / l2;
    const size_t row1 = qtok0 + 16 * w + (lane >> 2);
    const size_t row2 = row1 + 8;
    const int col = hoff + (lane & 3) * 2;
#pragma unroll
    for (int j = 0; j < 8; j++) {
        uint32_t hw, lw;
        split2(o[j][0] * inv1, o[j][1] * inv1, hw, lw);
        *(uint32_t*)(ch + row1 * DM + col + j * 8) = hw;
        *(uint32_t*)(cl + row1 * DM + col + j * 8) = lw;
        split2(o[j][2] * inv2, o[j][3] * inv2, hw, lw);
        *(uint32_t*)(ch + row2 * DM + col + j * 8) = hw;
        *(uint32_t*)(cl + row2 * DM + col + j * 8) = lw;
    }
}

// ---------------------------------------------------------------------------
// Transpose+split helpers
// ---------------------------------------------------------------------------
__device__ __forceinline__ void wsplit_tile(const float* W, __nv_bfloat16* Th,
                                            __nv_bfloat16* Tl, int K, int N,
                                            int n0, int k0)
{
    __shared__ float ts[32][33];
    int tx = threadIdx.x & 31, ty = threadIdx.x >> 5;
#pragma unroll
    for (int i = 0; i < 4; i++)
        ts[ty + i * 8][tx] = W[(size_t)(k0 + ty + i * 8) * N + n0 + tx];
    __syncthreads();
#pragma unroll
    for (int i = 0; i < 4; i++) {
        float vv = ts[tx][ty + i * 8];
        __nv_bfloat16 hb = __float2bfloat16(vv);
        size_t o = (size_t)(n0 + ty + i * 8) * K + k0 + tx;
        Th[o] = hb;
        Tl[o] = __float2bfloat16(vv - __bfloat162float(hb));
    }
}

__global__ __launch_bounds__(256)
void wsplit_qkvo(const float* __restrict__ Wq, const float* __restrict__ Wk,
                 const float* __restrict__ Wv, const float* __restrict__ Wo,
                 __nv_bfloat16* __restrict__ Th, __nv_bfloat16* __restrict__ Tl,
                 const float* __restrict__ bq, const float* __restrict__ bk,
                 const float* __restrict__ bv, float* __restrict__ bqkv)
{
    int z = blockIdx.z;
    if (z == 16) {
        int idx = blockIdx.y * 16 + blockIdx.x;
        if (idx < 24) {
            int l = idx / 6, i = (idx % 6) * 256 + threadIdx.x;
            float v = (i < 512) ? bq[l * 512 + i]
                    : (i < 1024) ? bk[l * 512 + i - 512]
                    : bv[l * 512 + i - 1024];
            bqkv[l * 1536 + i] = v;
        }
        return;
    }
    int l = z >> 2, tp = z & 3;
    const float* W = ((tp == 0) ? Wq : (tp == 1) ? Wk : (tp == 2) ? Wv : Wo)
                   + (size_t)l * DM * DM;
    size_t doff = (size_t)l * LSTRIDE + (size_t)tp * 262144;
    wsplit_tile(W, Th + doff, Tl + doff, DM, DM, blockIdx.x * 32, blockIdx.y * 32);
}

__global__ __launch_bounds__(256)
void wsplit_t(const float* __restrict__ W, __nv_bfloat16* __restrict__ Th,
              __nv_bfloat16* __restrict__ Tl, int K, int N,
              size_t src_lstride, size_t dst_lstride)
{
    int l = blockIdx.z;
    wsplit_tile(W + (size_t)l * src_lstride, Th + (size_t)l * dst_lstride,
                Tl + (size_t)l * dst_lstride, K, N, blockIdx.x * 32, blockIdx.y * 32);
}

__global__ __launch_bounds__(256)
void wsplit_w2x(const float* __restrict__ W2, __nv_bfloat16* __restrict__ Th,
                __nv_bfloat16* __restrict__ Tl,
                const float* __restrict__ x, __nv_bfloat16* __restrict__ xh,
                __nv_bfloat16* __restrict__ xl)
{
    int z = blockIdx.z;
    if (z < 4) {
        size_t doff = (size_t)z * LSTRIDE;
        wsplit_tile(W2 + (size_t)z * DFF * DM, Th + doff, Tl + doff,
                    DFF, DM, blockIdx.x * 32, blockIdx.y * 32);
        return;
    }
    size_t lin = (((size_t)(z - 4) * 1024 + blockIdx.y * 16 + blockIdx.x) * 256
                  + threadIdx.x) * 4;
    float4 val = *(const float4*)(x + lin);
    uint32_t h0, l0, h1, l1;
    split2(val.x, val.y, h0, l0);
    split2(val.z, val.w, h1, l1);
    *(uint2*)(xh + lin) = make_uint2(h0, h1);
    *(uint2*)(xl + lin) = make_uint2(l0, l1);
}

// ---------------------------------------------------------------------------
// LN: warp-per-row
// ---------------------------------------------------------------------------
__global__ __launch_bounds__(256)
void ln_kernel(const float* __restrict__ in, const float* __restrict__ g,
               const float* __restrict__ bb, float* __restrict__ out,
               __nv_bfloat16* __restrict__ oh, __nv_bfloat16* __restrict__ ol)
{
    int w = threadIdx.x >> 5, lane = threadIdx.x & 31;
    size_t row = (size_t)blockIdx.x * 8 + w;
    float4 v[4];
    float sum = 0.0f;
#pragma unroll
    for (int j = 0; j < 4; j++) {
        v[j] = *(const float4*)&in[row * DM + j * 128 + lane * 4];
        sum += v[j].x + v[j].y + v[j].z + v[j].w;
    }
#pragma unroll
    for (int off = 16; off > 0; off >>= 1)
        sum += __shfl_xor_sync(0xffffffffu, sum, off);
    float mu = sum * (1.0f / DM);
    float vs = 0.0f;
#pragma unroll
    for (int j = 0; j < 4; j++) {
        v[j].x -= mu; v[j].y -= mu; v[j].z -= mu; v[j].w -= mu;
        vs += v[j].x * v[j].x + v[j].y * v[j].y + v[j].z * v[j].z + v[j].w * v[j].w;
    }
#pragma unroll
    for (int off = 16; off > 0; off >>= 1)
        vs += __shfl_xor_sync(0xffffffffu, vs, off);
    float rstd = rsqrtf(vs * (1.0f / DM) + 1e-5f);
#pragma unroll
    for (int j = 0; j < 4; j++) {
        int c = j * 128 + lane * 4;
        float4 gv = *(const float4*)&g[c];
        float4 bv = *(const float4*)&bb[c];
        float4 o;
        o.x = v[j].x * rstd * gv.x + bv.x;
        o.y = v[j].y * rstd * gv.y + bv.y;
        o.z = v[j].z * rstd * gv.z + bv.z;
        o.w = v[j].w * rstd * gv.w + bv.w;
        *(float4*)&out[row * DM + c] = o;
        uint32_t h01, l01, h23, l23;
        split2(o.x, o.y, h01, l01);
        split2(o.z, o.w, h23, l23);
        *(uint2*)&oh[row * DM + c] = make_uint2(h01, h23);
        *(uint2*)&ol[row * DM + c] = make_uint2(l01, l23);
    }
}

// ---------------------------------------------------------------------------
// pool / head
// ---------------------------------------------------------------------------
__device__ __forceinline__ float block_sum(float v, float* red, int nwarps)
{
    int lane = threadIdx.x & 31, w = threadIdx.x >> 5;
#pragma unroll
    for (int off = 16; off > 0; off >>= 1)
        v += __shfl_xor_sync(0xffffffffu, v, off);
    if (lane == 0) red[w] = v;
    __syncthreads();
    if (w == 0) {
        float ts = (lane < nwarps) ? red[lane] : 0.0f;
#pragma unroll
        for (int off = 16; off > 0; off >>= 1)
            ts += __shfl_xor_sync(0xffffffffu, ts, off);
        if (lane == 0) red[0] = ts;
    }
    __syncthreads();
    float r = red[0];
    __syncthreads();
    return r;
}

__global__ __launch_bounds__(512)
void pool_kernel(const float* __restrict__ h, float* __restrict__ pooled)
{
    int b = blockIdx.x, d = threadIdx.x;
    const float* p = h + (size_t)b * S_ * DM + d;
    float s = 0.0f;
#pragma unroll 8
    for (int i = 0; i < S_; i++) s += p[(size_t)i * DM];
    pooled[b * DM + d] = s * (1.0f / S_);
}

__global__ __launch_bounds__(512)
void final_kernel(const float* __restrict__ pooled, const float* __restrict__ lng,
                  const float* __restrict__ lnb, const float* __restrict__ fcw,
                  const float* __restrict__ fcb, float* __restrict__ out)
{
    __shared__ float red[32];
    int b = blockIdx.x, d = threadIdx.x;
    float x = pooled[b * DM + d];
    float mu = block_sum(x, red, 16) * (1.0f / DM);
    float dx = x - mu;
    float var = block_sum(dx * dx, red, 16) * (1.0f / DM);
    float y = dx * rsqrtf(var + 1e-5f) * lng[d] + lnb[d];
    float z = block_sum(y * fcw[d], red, 16);
    if (d == 0) out[b] = 1.0f / (1.0f + expf(-(z + fcb[0])));
}

// ---------------------------------------------------------------------------
// launch
// ---------------------------------------------------------------------------
extern "C" void kernel_launch(void* const* d_in, const int* in_sizes, int n_in,
                              void* d_out, int out_size)
{
    const float* x    = (const float*)d_in[0];
    const float* Wp   = (const float*)d_in[1];
    const float* bp   = (const float*)d_in[2];
    const float* Wq   = (const float*)d_in[3];
    const float* bq   = (const float*)d_in[4];
    const float* Wk   = (const float*)d_in[5];
    const float* bk   = (const float*)d_in[6];
    const float* Wv   = (const float*)d_in[7];
    const float* bv   = (const float*)d_in[8];
    const float* Wo   = (const float*)d_in[9];
    const float* bo   = (const float*)d_in[10];
    const float* ln1g = (const float*)d_in[11];
    const float* ln1b = (const float*)d_in[12];
    const float* W1   = (const float*)d_in[13];
    const float* b1   = (const float*)d_in[14];
    const float* W2   = (const float*)d_in[15];
    const float* b2   = (const float*)d_in[16];
    const float* ln2g = (const float*)d_in[17];
    const float* ln2b = (const float*)d_in[18];
    const float* lng  = (const float*)d_in[19];
    const float* lnb  = (const float*)d_in[20];
    const float* fcw  = (const float*)d_in[21];
    const float* fcb  = (const float*)d_in[22];
    float* out = (float*)d_out;

    float *h, *tmp, *pooled, *bqkv;
    __nv_bfloat16 *xh, *xl, *hh, *hl, *ch, *cl, *wth, *wtl;
    __nv_bfloat16 *qh, *ql, *kh, *kl, *vh, *vl;
    cudaGetSymbolAddress((void**)&h, g_h);
    cudaGetSymbolAddress((void**)&tmp, g_tmp);
    cudaGetSymbolAddress((void**)&pooled, g_pool);
    cudaGetSymbolAddress((void**)&bqkv, g_bqkv);
    cudaGetSymbolAddress((void**)&xh, g_xh);
    cudaGetSymbolAddress((void**)&xl, g_xl);
    cudaGetSymbolAddress((void**)&hh, g_hh);
    cudaGetSymbolAddress((void**)&hl, g_hl);
    cudaGetSymbolAddress((void**)&ch, g_ch);
    cudaGetSymbolAddress((void**)&cl, g_cl);
    cudaGetSymbolAddress((void**)&wth, g_wth);
    cudaGetSymbolAddress((void**)&wtl, g_wtl);
    { void* p; cudaGetSymbolAddress(&p, g_q); qh = (__nv_bfloat16*)p; ql = qh + (size_t)NTOK * DM; }
    { void* p; cudaGetSymbolAddress(&p, g_k); kh = (__nv_bfloat16*)p; kl = kh + (size_t)NTOK * DM; }
    { void* p; cudaGetSymbolAddress(&p, g_v); vh = (__nv_bfloat16*)p; vl = vh + (size_t)NTOK * DM; }

    cudaFuncSetAttribute(gemm_mma<2,true,true>,  cudaFuncAttributeMaxDynamicSharedMemorySize, GSMEM_TOTAL);
    cudaFuncSetAttribute(gemm_mma<4,true,false>, cudaFuncAttributeMaxDynamicSharedMemorySize, GSMEM_TOTAL);
    cudaFuncSetAttribute(gemm_mma<3,false,true>, cudaFuncAttributeMaxDynamicSharedMemorySize, GSMEM_TOTAL);
    cudaFuncSetAttribute(gemm_mma<1,true,false>, cudaFuncAttributeMaxDynamicSharedMemorySize, GSMEM_TOTAL);
    cudaFuncSetAttribute(attn_mma, cudaFuncAttributeMaxDynamicSharedMemorySize, ATTN_SMEM);

    // ---- preprocessing: 4 launches ----
    wsplit_qkvo<<<dim3(16,16,17), 256>>>(Wq, Wk, Wv, Wo, wth+LBASE, wtl+LBASE,
                                         bq, bk, bv, bqkv);
    wsplit_t<<<dim3(16,64,1), 256>>>(Wp, wth, wtl, FEAT, DM, 0, 0);
    wsplit_t<<<dim3(64,16,NL), 256>>>(W1, wth+LBASE+1048576, wtl+LBASE+1048576,
                                      DM, DFF, (size_t)DM*DFF, LSTRIDE);
    wsplit_w2x<<<dim3(16,64,36), 256>>>(W2, wth+LBASE+2097152, wtl+LBASE+2097152,
                                        x, xh, xl);

    dim3 gDM(DM / 256, NTOK / 128);     // (2,128)
    dim3 gQKV(1536 / 256, NTOK / 128);  // (6,128)
    dim3 gFF(DFF / 256, NTOK / 128);    // (8,128)
    dim3 gAtt(S_ / 64, B_ * NH);

    gemm_mma<2,true,true><<<gDM, 256, GSMEM_TOTAL>>>(
        xh, xl, wth, wtl, bp, nullptr, h, hh, hl,
        nullptr, nullptr, nullptr, nullptr, DM, FEAT);

    for (int l = 0; l < NL; l++) {
        size_t b0 = LBASE + (size_t)l * LSTRIDE;
        gemm_mma<4,true,false><<<gQKV, 256, GSMEM_TOTAL>>>(
            hh, hl, wth+b0, wtl+b0, bqkv + l*1536, nullptr, nullptr,
            qh, ql, kh, kl, vh, vl, DM, DM);

        attn_mma<<<gAtt, 128, ATTN_SMEM>>>(qh, ql, kh, kl, vh, vl, ch, cl);

        gemm_mma<3,false,true><<<gDM, 256, GSMEM_TOTAL>>>(
            ch, cl, wth+b0+786432, wtl+b0+786432, bo + l*DM, h, tmp, nullptr, nullptr,
            nullptr, nullptr, nullptr, nullptr, DM, DM);
        ln_kernel<<<NTOK/8, 256>>>(tmp, ln1g + l*DM, ln1b + l*DM, h, hh, hl);

        gemm_mma<1,true,false><<<gFF, 256, GSMEM_TOTAL>>>(
            hh, hl, wth+b0+1048576, wtl+b0+1048576, b1 + l*DFF, nullptr, nullptr, xh, xl,
            nullptr, nullptr, nullptr, nullptr, DFF, DM);
        gemm_mma<3,false,true><<<gDM, 256, GSMEM_TOTAL>>>(
            xh, xl, wth+b0+2097152, wtl+b0+2097152, b2 + l*DM, h, tmp, nullptr, nullptr,
            nullptr, nullptr, nullptr, nullptr, DM, DFF);
        ln_kernel<<<NTOK/8, 256>>>(tmp, ln2g + l*DM, ln2b + l*DM, h, hh, hl);
    }

    pool_kernel<<<B_, 512>>>(h, pooled);
    final_kernel<<<B_, 512>>>(pooled, lng, lnb, fcw, fcb, out);
}

// round 15
// speedup vs baseline: 1.2009x; 1.2009x over previous
#include <cuda_runtime.h>
#include <cuda_bf16.h>
#include <math.h>
#include <stdint.h>

#define B_     32
#define S_     512
#define DM     512
#define NH     8
#define NL     4
#define DFF    2048
#define FEAT   2048
#define NTOK   (B_ * S_)

// ---------------- scratch ----------------
__device__ float g_h   [NTOK * DM];
__device__ float g_q   [NTOK * DM];   // reused: qh/ql bf16
__device__ float g_k   [NTOK * DM];   // reused: kh/kl bf16
__device__ float g_v   [NTOK * DM];   // reused: vh/vl bf16
__device__ float g_tmp [NTOK * DM];
__device__ float g_pool[B_ * DM];
__device__ float g_bqkv[NL * 1536];

__device__ __nv_bfloat16 g_xh[NTOK * FEAT];
__device__ __nv_bfloat16 g_xl[NTOK * FEAT];
__device__ __nv_bfloat16 g_hh[NTOK * DM];
__device__ __nv_bfloat16 g_hl[NTOK * DM];
__device__ __nv_bfloat16 g_ch[NTOK * DM];
__device__ __nv_bfloat16 g_cl[NTOK * DM];
#define WTOT 13631488
__device__ __nv_bfloat16 g_wth[WTOT];
__device__ __nv_bfloat16 g_wtl[WTOT];

#define LBASE   1048576
#define LSTRIDE 3145728

// ---------------- helpers ----------------
__device__ __forceinline__ uint32_t smem_u32(const void* p) {
    uint32_t a;
    asm("{ .reg .u64 t; cvta.to.shared.u64 t, %1; cvt.u32.u64 %0, t; }" : "=r"(a) : "l"(p));
    return a;
}
__device__ __forceinline__ void cp16(uint32_t s, const void* g) {
    asm volatile("cp.async.cg.shared.global [%0], [%1], 16;" :: "r"(s), "l"(g));
}
#define CP_COMMIT() asm volatile("cp.async.commit_group;" ::: "memory")

__device__ __forceinline__ void ldm4(uint32_t* r, uint32_t addr) {
    asm volatile("ldmatrix.sync.aligned.m8n8.x4.shared.b16 {%0,%1,%2,%3}, [%4];"
                 : "=r"(r[0]), "=r"(r[1]), "=r"(r[2]), "=r"(r[3]) : "r"(addr));
}
__device__ __forceinline__ void ldm4t(uint32_t* r, uint32_t addr) {
    asm volatile("ldmatrix.sync.aligned.m8n8.x4.trans.shared.b16 {%0,%1,%2,%3}, [%4];"
                 : "=r"(r[0]), "=r"(r[1]), "=r"(r[2]), "=r"(r[3]) : "r"(addr));
}
__device__ __forceinline__ void mma16816(float* c, const uint32_t* a, const uint32_t* b) {
    asm volatile(
        "mma.sync.aligned.m16n8k16.row.col.f32.bf16.bf16.f32 "
        "{%0,%1,%2,%3}, {%4,%5,%6,%7}, {%8,%9}, {%0,%1,%2,%3};"
        : "+f"(c[0]), "+f"(c[1]), "+f"(c[2]), "+f"(c[3])
        : "r"(a[0]), "r"(a[1]), "r"(a[2]), "r"(a[3]), "r"(b[0]), "r"(b[1]));
}
__device__ __forceinline__ void split2(float a, float b, uint32_t& hi, uint32_t& lo) {
    __nv_bfloat162 h = __floats2bfloat162_rn(a, b);
    __nv_bfloat162 l = __floats2bfloat162_rn(a - __bfloat162float(h.x),
                                             b - __bfloat162float(h.y));
    hi = *(uint32_t*)&h;
    lo = *(uint32_t*)&l;
}

// ---------------------------------------------------------------------------
// Split-bf16 HMMA GEMM (R11 config — best measured): BM=BN=128, BK=32,
// 256 thr, 3-stage cp.async, 2 CTAs/SM, term-major inner loop.
// EPI: 0 bias, 1 +relu, 2 +posenc, 3 +residual, 4 QKV-routed split output.
// ---------------------------------------------------------------------------
#define GSTAGE 32768
#define GSMEM_TOTAL (3 * GSTAGE)

template<int EPI, bool WSPLIT, bool WF32>
__global__ __launch_bounds__(256, 2)
void gemm_mma(const __nv_bfloat16* __restrict__ Ah, const __nv_bfloat16* __restrict__ Al,
              const __nv_bfloat16* __restrict__ Bh, const __nv_bfloat16* __restrict__ Bl,
              const float* __restrict__ bias, const float* __restrict__ res,
              float* __restrict__ Cf, __nv_bfloat16* __restrict__ Ch,
              __nv_bfloat16* __restrict__ Cl,
              __nv_bfloat16* __restrict__ Ch2, __nv_bfloat16* __restrict__ Cl2,
              __nv_bfloat16* __restrict__ Ch3, __nv_bfloat16* __restrict__ Cl3,
              int N, int K)
{
    extern __shared__ char smem[];
    const uint32_t sb = smem_u32(smem);
    const int t = threadIdx.x, lane = t & 31, wid = t >> 5;
    const int wm = wid & 1, wn = wid >> 1;
    const int m0 = blockIdx.y << 7, n0 = blockIdx.x << 7;

    const int lr = t >> 1, lc0 = (t & 1) * 2;
    const int lsw = (lr & 6) >> 1;
    const char* gA_h = (const char*)(Ah + (size_t)(m0 + lr) * K);
    const char* gA_l = (const char*)(Al + (size_t)(m0 + lr) * K);
    const char* gB_h = (const char*)(Bh + (size_t)(n0 + lr) * K);
    const char* gB_l = (const char*)(Bl + (size_t)(n0 + lr) * K);

    auto load_stage = [&](int buf, int k0) {
        uint32_t base = sb + buf * GSTAGE;
#pragma unroll
        for (int c = lc0; c < lc0 + 2; c++) {
            uint32_t so = (uint32_t)(lr * 64 + ((c ^ lsw) << 4));
            size_t go = (size_t)(k0 + c * 8) * 2;
            cp16(base + so,          gA_h + go);
            cp16(base + 8192 + so,   gA_l + go);
            cp16(base + 16384 + so,  gB_h + go);
            cp16(base + 24576 + so,  gB_l + go);
        }
        CP_COMMIT();
    };

    const int csa = (lane >> 4) & 1;
    const int csb = (lane >> 3) & 1;
    uint32_t offA[4], sA[4];
#pragma unroll
    for (int mi = 0; mi < 4; mi++) {
        int r = wm * 64 + mi * 16 + (lane & 15);
        offA[mi] = r * 64;
        sA[mi] = (r & 6) >> 1;
    }
    uint32_t offB[2], sB[2];
#pragma unroll
    for (int g = 0; g < 2; g++) {
        int r = wn * 32 + g * 16 + (lane & 7) + ((lane & 16) >> 1);
        offB[g] = r * 64;
        sB[g] = (r & 6) >> 1;
    }

    float acc[4][4][4];
#pragma unroll
    for (int i = 0; i < 4; i++)
#pragma unroll
        for (int j = 0; j < 4; j++)
#pragma unroll
            for (int e = 0; e < 4; e++) acc[i][j][e] = 0.0f;

    const int nst = K >> 5;
    load_stage(0, 0);
    load_stage(1, 32);

    int buf = 0;
    for (int st = 0; st < nst; st++) {
        if (st + 2 < nst) asm volatile("cp.async.wait_group 1;" ::: "memory");
        else              asm volatile("cp.async.wait_group 0;" ::: "memory");
        __syncthreads();
        if (st + 2 < nst) {
            int nb = buf + 2; if (nb >= 3) nb -= 3;
            load_stage(nb, (st + 2) * 32);
        }

        uint32_t base = sb + buf * GSTAGE;
#pragma unroll
        for (int ks = 0; ks < 2; ks++) {
            uint32_t ah[4][4], al[4][4];
#pragma unroll
            for (int mi = 0; mi < 4; mi++) {
                uint32_t ca = (((2 * ks + csa) ^ sA[mi]) << 4);
                ldm4(ah[mi], base + offA[mi] + ca);
                ldm4(al[mi], base + 8192 + offA[mi] + ca);
            }
#pragma unroll
            for (int g = 0; g < 2; g++) {
                uint32_t cb = (((2 * ks + csb) ^ sB[g]) << 4);
                uint32_t rh[4], rl[4];
                ldm4(rh, base + 16384 + offB[g] + cb);
                ldm4(rl, base + 24576 + offB[g] + cb);
#pragma unroll
                for (int mi = 0; mi < 4; mi++) {
                    mma16816(acc[mi][2*g],   ah[mi], &rh[0]);
                    mma16816(acc[mi][2*g+1], ah[mi], &rh[2]);
                }
#pragma unroll
                for (int mi = 0; mi < 4; mi++) {
                    mma16816(acc[mi][2*g],   ah[mi], &rl[0]);
                    mma16816(acc[mi][2*g+1], ah[mi], &rl[2]);
                }
#pragma unroll
                for (int mi = 0; mi < 4; mi++) {
                    mma16816(acc[mi][2*g],   al[mi], &rh[0]);
                    mma16816(acc[mi][2*g+1], al[mi], &rh[2]);
                }
            }
        }
        buf++; if (buf == 3) buf = 0;
    }

    // ---- epilogue ----
    const float kPE = (float)(-9.210340371976184 / 512.0);
    const int rbase = m0 + wm * 64 + (lane >> 2);
    const int cbase = n0 + wn * 32 + (lane & 3) * 2;
    __nv_bfloat16 *Oh = Ch, *Ol = Cl;
    if (EPI == 4) {
        const int sel = n0 >> 9;
        Oh = (sel == 0) ? Ch : (sel == 1) ? Ch2 : Ch3;
        Ol = (sel == 0) ? Cl : (sel == 1) ? Cl2 : Cl3;
    }
#pragma unroll
    for (int mi = 0; mi < 4; mi++) {
#pragma unroll
        for (int half = 0; half < 2; half++) {
            const int row = rbase + mi * 16 + half * 8;
            const int s = row & (S_ - 1);
#pragma unroll
            for (int ni = 0; ni < 4; ni++) {
                const int col = cbase + ni * 8;
                const int ocol = (EPI == 4) ? (col & 511) : col;
                float vx = acc[mi][ni][2 * half + 0];
                float vy = acc[mi][ni][2 * half + 1];
                float2 bb = *(const float2*)(bias + col);
                vx += bb.x; vy += bb.y;
                if (EPI == 1) { vx = fmaxf(vx, 0.0f); vy = fmaxf(vy, 0.0f); }
                if (EPI == 2) {
                    float a = (float)s * expf((float)col * kPE);
                    vx += sinf(a); vy += cosf(a);
                }
                if (EPI == 3) {
                    float2 rr = *(const float2*)(res + (size_t)row * N + col);
                    vx += rr.x; vy += rr.y;
                }
                if (WF32)
                    *(float2*)(Cf + (size_t)row * N + ocol) = make_float2(vx, vy);
                if (WSPLIT) {
                    uint32_t hw, lw;
                    split2(vx, vy, hw, lw);
                    *(uint32_t*)(Oh + (size_t)row * N + ocol) = hw;
                    *(uint32_t*)(Ol + (size_t)row * N + ocol) = lw;
                }
            }
        }
    }
}

// ---------------------------------------------------------------------------
// Split-bf16 HMMA flash attention, K/V double-buffered.
// Smem: Qh Ql | buf0{Kh Kl Vh Vl} | buf1{Kh Kl Vh Vl} = 10 tiles.
// ---------------------------------------------------------------------------
#define AST 72
#define ATILE (64 * AST)
#define ATTN_SMEM (10 * ATILE * 2)   // 92160 B

__global__ __launch_bounds__(128)
void attn_mma(const __nv_bfloat16* __restrict__ qh, const __nv_bfloat16* __restrict__ ql,
              const __nv_bfloat16* __restrict__ kh, const __nv_bfloat16* __restrict__ kl,
              const __nv_bfloat16* __restrict__ vh, const __nv_bfloat16* __restrict__ vl,
              __nv_bfloat16* __restrict__ ch, __nv_bfloat16* __restrict__ cl)
{
    extern __shared__ __nv_bfloat16 smb[];
    const uint32_t sq = smem_u32(smb);
    const int t = threadIdx.x, lane = t & 31, w = t >> 5;
    const int b = blockIdx.y >> 3, h = blockIdx.y & 7;
    const int hoff = h << 6;
    const size_t btok0 = (size_t)b * S_;
    const size_t qtok0 = btok0 + ((size_t)blockIdx.x << 6);

    const int lr = t >> 1, lc0 = (t & 1) * 4;

    auto load_kv = [&](int buf, int kt) {
        uint32_t kb = (2 + 4 * buf) * ATILE;
        size_t tok = btok0 + kt * 64 + lr;
        const __nv_bfloat16* gk_h = kh + tok * DM + hoff;
        const __nv_bfloat16* gk_l = kl + tok * DM + hoff;
        const __nv_bfloat16* gv_h = vh + tok * DM + hoff;
        const __nv_bfloat16* gv_l = vl + tok * DM + hoff;
#pragma unroll
        for (int c = lc0; c < lc0 + 4; c++) {
            cp16(sq + (kb             + lr * AST + c * 8) * 2, gk_h + c * 8);
            cp16(sq + (kb + ATILE     + lr * AST + c * 8) * 2, gk_l + c * 8);
            cp16(sq + (kb + 2 * ATILE + lr * AST + c * 8) * 2, gv_h + c * 8);
            cp16(sq + (kb + 3 * ATILE + lr * AST + c * 8) * 2, gv_l + c * 8);
        }
        CP_COMMIT();
    };

    {
        const __nv_bfloat16* gq_h = qh + (qtok0 + lr) * DM + hoff;
        const __nv_bfloat16* gq_l = ql + (qtok0 + lr) * DM + hoff;
#pragma unroll
        for (int c = lc0; c < lc0 + 4; c++) {
            cp16(sq + (lr * AST + c * 8) * 2,         gq_h + c * 8);
            cp16(sq + (ATILE + lr * AST + c * 8) * 2, gq_l + c * 8);
        }
        CP_COMMIT();
    }
    load_kv(0, 0);

    float m1 = -INFINITY, m2 = -INFINITY, l1 = 0.0f, l2 = 0.0f;
    float o[8][4];
#pragma unroll
    for (int j = 0; j < 8; j++)
#pragma unroll
        for (int e = 0; e < 4; e++) o[j][e] = 0.0f;

    const uint32_t a_off = ((16 * w + (lane & 15)) * AST + ((lane >> 4) << 3)) * 2;
    const uint32_t k_row = (lane & 7) + ((lane & 16) >> 1);
    const uint32_t k_col = (((lane >> 3) & 1) << 3);
    const uint32_t v_off = ((lane & 15) * AST + ((lane >> 4) << 3)) * 2;

    for (int kt = 0; kt < 8; kt++) {
        const int buf = kt & 1;
        __syncthreads();                       // guard (kt-1)^1 buffer reuse
        if (kt + 1 < 8) {
            load_kv((kt + 1) & 1, kt + 1);
            asm volatile("cp.async.wait_group 1;" ::: "memory");
        } else {
            asm volatile("cp.async.wait_group 0;" ::: "memory");
        }
        __syncthreads();

        const uint32_t KH = (2 + 4 * buf) * ATILE;
        const uint32_t KL = KH + ATILE;
        const uint32_t VH = KH + 2 * ATILE;
        const uint32_t VL = KH + 3 * ATILE;

        float c_[8][4];
#pragma unroll
        for (int n = 0; n < 8; n++)
#pragma unroll
            for (int e = 0; e < 4; e++) c_[n][e] = 0.0f;

#pragma unroll
        for (int kc = 0; kc < 4; kc++) {
            uint32_t aqh[4], aql[4];
            ldm4(aqh, sq + a_off + kc * 32);
            ldm4(aql, sq + ATILE * 2 + a_off + kc * 32);
#pragma unroll
            for (int g = 0; g < 4; g++) {
                uint32_t rh[4], rl[4];
                uint32_t ko = ((g * 16 + k_row) * AST + kc * 16 + k_col) * 2;
                ldm4(rh, sq + KH * 2 + ko);
                ldm4(rl, sq + KL * 2 + ko);
                mma16816(c_[2*g],   aqh, &rh[0]);
                mma16816(c_[2*g+1], aqh, &rh[2]);
                mma16816(c_[2*g],   aqh, &rl[0]);
                mma16816(c_[2*g+1], aqh, &rl[2]);
                mma16816(c_[2*g],   aql, &rh[0]);
                mma16816(c_[2*g+1], aql, &rh[2]);
            }
        }

        float mx1 = -INFINITY, mx2 = -INFINITY;
#pragma unroll
        for (int n = 0; n < 8; n++) {
#pragma unroll
            for (int e = 0; e < 4; e++) c_[n][e] *= 0.125f;
            mx1 = fmaxf(mx1, fmaxf(c_[n][0], c_[n][1]));
            mx2 = fmaxf(mx2, fmaxf(c_[n][2], c_[n][3]));
        }
#pragma unroll
        for (int off = 1; off < 4; off <<= 1) {
            mx1 = fmaxf(mx1, __shfl_xor_sync(0xffffffffu, mx1, off));
            mx2 = fmaxf(mx2, __shfl_xor_sync(0xffffffffu, mx2, off));
        }
        float mn1 = fmaxf(m1, mx1), mn2 = fmaxf(m2, mx2);
        float corr1 = __expf(m1 - mn1), corr2 = __expf(m2 - mn2);
        m1 = mn1; m2 = mn2;
        float s1 = 0.0f, s2 = 0.0f;
#pragma unroll
        for (int n = 0; n < 8; n++) {
            c_[n][0] = __expf(c_[n][0] - mn1);
            c_[n][1] = __expf(c_[n][1] - mn1);
            c_[n][2] = __expf(c_[n][2] - mn2);
            c_[n][3] = __expf(c_[n][3] - mn2);
            s1 += c_[n][0] + c_[n][1];
            s2 += c_[n][2] + c_[n][3];
        }
#pragma unroll
        for (int off = 1; off < 4; off <<= 1) {
            s1 += __shfl_xor_sync(0xffffffffu, s1, off);
            s2 += __shfl_xor_sync(0xffffffffu, s2, off);
        }
        l1 = l1 * corr1 + s1;
        l2 = l2 * corr2 + s2;
#pragma unroll
        for (int j = 0; j < 8; j++) {
            o[j][0] *= corr1; o[j][1] *= corr1;
            o[j][2] *= corr2; o[j][3] *= corr2;
        }

#pragma unroll
        for (int kc = 0; kc < 4; kc++) {
            uint32_t ph[4], pl[4];
            split2(c_[2*kc][0],   c_[2*kc][1],   ph[0], pl[0]);
            split2(c_[2*kc][2],   c_[2*kc][3],   ph[1], pl[1]);
            split2(c_[2*kc+1][0], c_[2*kc+1][1], ph[2], pl[2]);
            split2(c_[2*kc+1][2], c_[2*kc+1][3], ph[3], pl[3]);
#pragma unroll
            for (int j = 0; j < 4; j++) {
                uint32_t rvh[4], rvl[4];
                uint32_t vo = (kc * 16 * AST + j * 16) * 2 + v_off;
                ldm4t(rvh, sq + VH * 2 + vo);
                ldm4t(rvl, sq + VL * 2 + vo);
                mma16816(o[2*j],   ph, &rvh[0]);
                mma16816(o[2*j+1], ph, &rvh[2]);
                mma16816(o[2*j],   ph, &rvl[0]);
                mma16816(o[2*j+1], ph, &rvl[2]);
                mma16816(o[2*j],   pl, &rvh[0]);
                mma16816(o[2*j+1], pl, &rvh[2]);
            }
        }
    }

    float inv1 = 1.0f / l1, inv2 = 1.0f / l2;
    const size_t row1 = qtok0 + 16 * w + (lane >> 2);
    const size_t row2 = row1 + 8;
    const int col = hoff + (lane & 3) * 2;
#pragma unroll
    for (int j = 0; j < 8; j++) {
        uint32_t hw, lw;
        split2(o[j][0] * inv1, o[j][1] * inv1, hw, lw);
        *(uint32_t*)(ch + row1 * DM + col + j * 8) = hw;
        *(uint32_t*)(cl + row1 * DM + col + j * 8) = lw;
        split2(o[j][2] * inv2, o[j][3] * inv2, hw, lw);
        *(uint32_t*)(ch + row2 * DM + col + j * 8) = hw;
        *(uint32_t*)(cl + row2 * DM + col + j * 8) = lw;
    }
}

// ---------------------------------------------------------------------------
// Transpose+split helpers
// ---------------------------------------------------------------------------
__device__ __forceinline__ void wsplit_tile(const float* W, __nv_bfloat16* Th,
                                            __nv_bfloat16* Tl, int K, int N,
                                            int n0, int k0)
{
    __shared__ float ts[32][33];
    int tx = threadIdx.x & 31, ty = threadIdx.x >> 5;
#pragma unroll
    for (int i = 0; i < 4; i++)
        ts[ty + i * 8][tx] = W[(size_t)(k0 + ty + i * 8) * N + n0 + tx];
    __syncthreads();
#pragma unroll
    for (int i = 0; i < 4; i++) {
        float vv = ts[tx][ty + i * 8];
        __nv_bfloat16 hb = __float2bfloat16(vv);
        size_t o = (size_t)(n0 + ty + i * 8) * K + k0 + tx;
        Th[o] = hb;
        Tl[o] = __float2bfloat16(vv - __bfloat162float(hb));
    }
}

__global__ __launch_bounds__(256)
void wsplit_qkvo(const float* __restrict__ Wq, const float* __restrict__ Wk,
                 const float* __restrict__ Wv, const float* __restrict__ Wo,
                 __nv_bfloat16* __restrict__ Th, __nv_bfloat16* __restrict__ Tl,
                 const float* __restrict__ bq, const float* __restrict__ bk,
                 const float* __restrict__ bv, float* __restrict__ bqkv)
{
    int z = blockIdx.z;
    if (z == 16) {
        int idx = blockIdx.y * 16 + blockIdx.x;
        if (idx < 24) {
            int l = idx / 6, i = (idx % 6) * 256 + threadIdx.x;
            float v = (i < 512) ? bq[l * 512 + i]
                    : (i < 1024) ? bk[l * 512 + i - 512]
                    : bv[l * 512 + i - 1024];
            bqkv[l * 1536 + i] = v;
        }
        return;
    }
    int l = z >> 2, tp = z & 3;
    const float* W = ((tp == 0) ? Wq : (tp == 1) ? Wk : (tp == 2) ? Wv : Wo)
                   + (size_t)l * DM * DM;
    size_t doff = (size_t)l * LSTRIDE + (size_t)tp * 262144;
    wsplit_tile(W, Th + doff, Tl + doff, DM, DM, blockIdx.x * 32, blockIdx.y * 32);
}

__global__ __launch_bounds__(256)
void wsplit_t(const float* __restrict__ W, __nv_bfloat16* __restrict__ Th,
              __nv_bfloat16* __restrict__ Tl, int K, int N,
              size_t src_lstride, size_t dst_lstride)
{
    int l = blockIdx.z;
    wsplit_tile(W + (size_t)l * src_lstride, Th + (size_t)l * dst_lstride,
                Tl + (size_t)l * dst_lstride, K, N, blockIdx.x * 32, blockIdx.y * 32);
}

__global__ __launch_bounds__(256)
void wsplit_w2x(const float* __restrict__ W2, __nv_bfloat16* __restrict__ Th,
                __nv_bfloat16* __restrict__ Tl,
                const float* __restrict__ x, __nv_bfloat16* __restrict__ xh,
                __nv_bfloat16* __restrict__ xl)
{
    int z = blockIdx.z;
    if (z < 4) {
        size_t doff = (size_t)z * LSTRIDE;
        wsplit_tile(W2 + (size_t)z * DFF * DM, Th + doff, Tl + doff,
                    DFF, DM, blockIdx.x * 32, blockIdx.y * 32);
        return;
    }
    size_t lin = (((size_t)(z - 4) * 1024 + blockIdx.y * 16 + blockIdx.x) * 256
                  + threadIdx.x) * 4;
    float4 val = *(const float4*)(x + lin);
    uint32_t h0, l0, h1, l1;
    split2(val.x, val.y, h0, l0);
    split2(val.z, val.w, h1, l1);
    *(uint2*)(xh + lin) = make_uint2(h0, h1);
    *(uint2*)(xl + lin) = make_uint2(l0, l1);
}

// ---------------------------------------------------------------------------
// LN: warp-per-row
// ---------------------------------------------------------------------------
__global__ __launch_bounds__(256)
void ln_kernel(const float* __restrict__ in, const float* __restrict__ g,
               const float* __restrict__ bb, float* __restrict__ out,
               __nv_bfloat16* __restrict__ oh, __nv_bfloat16* __restrict__ ol)
{
    int w = threadIdx.x >> 5, lane = threadIdx.x & 31;
    size_t row = (size_t)blockIdx.x * 8 + w;
    float4 v[4];
    float sum = 0.0f;
#pragma unroll
    for (int j = 0; j < 4; j++) {
        v[j] = *(const float4*)&in[row * DM + j * 128 + lane * 4];
        sum += v[j].x + v[j].y + v[j].z + v[j].w;
    }
#pragma unroll
    for (int off = 16; off > 0; off >>= 1)
        sum += __shfl_xor_sync(0xffffffffu, sum, off);
    float mu = sum * (1.0f / DM);
    float vs = 0.0f;
#pragma unroll
    for (int j = 0; j < 4; j++) {
        v[j].x -= mu; v[j].y -= mu; v[j].z -= mu; v[j].w -= mu;
        vs += v[j].x * v[j].x + v[j].y * v[j].y + v[j].z * v[j].z + v[j].w * v[j].w;
    }
#pragma unroll
    for (int off = 16; off > 0; off >>= 1)
        vs += __shfl_xor_sync(0xffffffffu, vs, off);
    float rstd = rsqrtf(vs * (1.0f / DM) + 1e-5f);
#pragma unroll
    for (int j = 0; j < 4; j++) {
        int c = j * 128 + lane * 4;
        float4 gv = *(const float4*)&g[c];
        float4 bv = *(const float4*)&bb[c];
        float4 o;
        o.x = v[j].x * rstd * gv.x + bv.x;
        o.y = v[j].y * rstd * gv.y + bv.y;
        o.z = v[j].z * rstd * gv.z + bv.z;
        o.w = v[j].w * rstd * gv.w + bv.w;
        *(float4*)&out[row * DM + c] = o;
        uint32_t h01, l01, h23, l23;
        split2(o.x, o.y, h01, l01);
        split2(o.z, o.w, h23, l23);
        *(uint2*)&oh[row * DM + c] = make_uint2(h01, h23);
        *(uint2*)&ol[row * DM + c] = make_uint2(l01, l23);
    }
}

// ---------------------------------------------------------------------------
// pool / head
// ---------------------------------------------------------------------------
__device__ __forceinline__ float block_sum(float v, float* red, int nwarps)
{
    int lane = threadIdx.x & 31, w = threadIdx.x >> 5;
#pragma unroll
    for (int off = 16; off > 0; off >>= 1)
        v += __shfl_xor_sync(0xffffffffu, v, off);
    if (lane == 0) red[w] = v;
    __syncthreads();
    if (w == 0) {
        float ts = (lane < nwarps) ? red[lane] : 0.0f;
#pragma unroll
        for (int off = 16; off > 0; off >>= 1)
            ts += __shfl_xor_sync(0xffffffffu, ts, off);
        if (lane == 0) red[0] = ts;
    }
    __syncthreads();
    float r = red[0];
    __syncthreads();
    return r;
}

__global__ __launch_bounds__(512)
void pool_kernel(const float* __restrict__ h, float* __restrict__ pooled)
{
    int b = blockIdx.x, d = threadIdx.x;
    const float* p = h + (size_t)b * S_ * DM + d;
    float s = 0.0f;
#pragma unroll 8
    for (int i = 0; i < S_; i++) s += p[(size_t)i * DM];
    pooled[b * DM + d] = s * (1.0f / S_);
}

__global__ __launch_bounds__(512)
void final_kernel(const float* __restrict__ pooled, const float* __restrict__ lng,
                  const float* __restrict__ lnb, const float* __restrict__ fcw,
                  const float* __restrict__ fcb, float* __restrict__ out)
{
    __shared__ float red[32];
    int b = blockIdx.x, d = threadIdx.x;
    float x = pooled[b * DM + d];
    float mu = block_sum(x, red, 16) * (1.0f / DM);
    float dx = x - mu;
    float var = block_sum(dx * dx, red, 16) * (1.0f / DM);
    float y = dx * rsqrtf(var + 1e-5f) * lng[d] + lnb[d];
    float z = block_sum(y * fcw[d], red, 16);
    if (d == 0) out[b] = 1.0f / (1.0f + expf(-(z + fcb[0])));
}

// ---------------------------------------------------------------------------
// launch
// ---------------------------------------------------------------------------
extern "C" void kernel_launch(void* const* d_in, const int* in_sizes, int n_in,
                              void* d_out, int out_size)
{
    const float* x    = (const float*)d_in[0];
    const float* Wp   = (const float*)d_in[1];
    const float* bp   = (const float*)d_in[2];
    const float* Wq   = (const float*)d_in[3];
    const float* bq   = (const float*)d_in[4];
    const float* Wk   = (const float*)d_in[5];
    const float* bk   = (const float*)d_in[6];
    const float* Wv   = (const float*)d_in[7];
    const float* bv   = (const float*)d_in[8];
    const float* Wo   = (const float*)d_in[9];
    const float* bo   = (const float*)d_in[10];
    const float* ln1g = (const float*)d_in[11];
    const float* ln1b = (const float*)d_in[12];
    const float* W1   = (const float*)d_in[13];
    const float* b1   = (const float*)d_in[14];
    const float* W2   = (const float*)d_in[15];
    const float* b2   = (const float*)d_in[16];
    const float* ln2g = (const float*)d_in[17];
    const float* ln2b = (const float*)d_in[18];
    const float* lng  = (const float*)d_in[19];
    const float* lnb  = (const float*)d_in[20];
    const float* fcw  = (const float*)d_in[21];
    const float* fcb  = (const float*)d_in[22];
    float* out = (float*)d_out;

    float *h, *tmp, *pooled, *bqkv;
    __nv_bfloat16 *xh, *xl, *hh, *hl, *ch, *cl, *wth, *wtl;
    __nv_bfloat16 *qh, *ql, *kh, *kl, *vh, *vl;
    cudaGetSymbolAddress((void**)&h, g_h);
    cudaGetSymbolAddress((void**)&tmp, g_tmp);
    cudaGetSymbolAddress((void**)&pooled, g_pool);
    cudaGetSymbolAddress((void**)&bqkv, g_bqkv);
    cudaGetSymbolAddress((void**)&xh, g_xh);
    cudaGetSymbolAddress((void**)&xl, g_xl);
    cudaGetSymbolAddress((void**)&hh, g_hh);
    cudaGetSymbolAddress((void**)&hl, g_hl);
    cudaGetSymbolAddress((void**)&ch, g_ch);
    cudaGetSymbolAddress((void**)&cl, g_cl);
    cudaGetSymbolAddress((void**)&wth, g_wth);
    cudaGetSymbolAddress((void**)&wtl, g_wtl);
    { void* p; cudaGetSymbolAddress(&p, g_q); qh = (__nv_bfloat16*)p; ql = qh + (size_t)NTOK * DM; }
    { void* p; cudaGetSymbolAddress(&p, g_k); kh = (__nv_bfloat16*)p; kl = kh + (size_t)NTOK * DM; }
    { void* p; cudaGetSymbolAddress(&p, g_v); vh = (__nv_bfloat16*)p; vl = vh + (size_t)NTOK * DM; }

    cudaFuncSetAttribute(gemm_mma<2,true,true>,  cudaFuncAttributeMaxDynamicSharedMemorySize, GSMEM_TOTAL);
    cudaFuncSetAttribute(gemm_mma<4,true,false>, cudaFuncAttributeMaxDynamicSharedMemorySize, GSMEM_TOTAL);
    cudaFuncSetAttribute(gemm_mma<3,false,true>, cudaFuncAttributeMaxDynamicSharedMemorySize, GSMEM_TOTAL);
    cudaFuncSetAttribute(gemm_mma<1,true,false>, cudaFuncAttributeMaxDynamicSharedMemorySize, GSMEM_TOTAL);
    cudaFuncSetAttribute(attn_mma, cudaFuncAttributeMaxDynamicSharedMemorySize, ATTN_SMEM);

    // ---- preprocessing: 4 launches ----
    wsplit_qkvo<<<dim3(16,16,17), 256>>>(Wq, Wk, Wv, Wo, wth+LBASE, wtl+LBASE,
                                         bq, bk, bv, bqkv);
    wsplit_t<<<dim3(16,64,1), 256>>>(Wp, wth, wtl, FEAT, DM, 0, 0);
    wsplit_t<<<dim3(64,16,NL), 256>>>(W1, wth+LBASE+1048576, wtl+LBASE+1048576,
                                      DM, DFF, (size_t)DM*DFF, LSTRIDE);
    wsplit_w2x<<<dim3(16,64,36), 256>>>(W2, wth+LBASE+2097152, wtl+LBASE+2097152,
                                        x, xh, xl);

    dim3 gDM(DM / 128, NTOK / 128);
    dim3 gQKV(1536 / 128, NTOK / 128);
    dim3 gFF(DFF / 128, NTOK / 128);
    dim3 gAtt(S_ / 64, B_ * NH);

    gemm_mma<2,true,true><<<gDM, 256, GSMEM_TOTAL>>>(
        xh, xl, wth, wtl, bp, nullptr, h, hh, hl,
        nullptr, nullptr, nullptr, nullptr, DM, FEAT);

    for (int l = 0; l < NL; l++) {
        size_t b0 = LBASE + (size_t)l * LSTRIDE;
        gemm_mma<4,true,false><<<gQKV, 256, GSMEM_TOTAL>>>(
            hh, hl, wth+b0, wtl+b0, bqkv + l*1536, nullptr, nullptr,
            qh, ql, kh, kl, vh, vl, DM, DM);

        attn_mma<<<gAtt, 128, ATTN_SMEM>>>(qh, ql, kh, kl, vh, vl, ch, cl);

        gemm_mma<3,false,true><<<gDM, 256, GSMEM_TOTAL>>>(
            ch, cl, wth+b0+786432, wtl+b0+786432, bo + l*DM, h, tmp, nullptr, nullptr,
            nullptr, nullptr, nullptr, nullptr, DM, DM);
        ln_kernel<<<NTOK/8, 256>>>(tmp, ln1g + l*DM, ln1b + l*DM, h, hh, hl);

        gemm_mma<1,true,false><<<gFF, 256, GSMEM_TOTAL>>>(
            hh, hl, wth+b0+1048576, wtl+b0+1048576, b1 + l*DFF, nullptr, nullptr, xh, xl,
            nullptr, nullptr, nullptr, nullptr, DFF, DM);
        gemm_mma<3,false,true><<<gDM, 256, GSMEM_TOTAL>>>(
            xh, xl, wth+b0+2097152, wtl+b0+2097152, b2 + l*DM, h, tmp, nullptr, nullptr,
            nullptr, nullptr, nullptr, nullptr, DM, DFF);
        ln_kernel<<<NTOK/8, 256>>>(tmp, ln2g + l*DM, ln2b + l*DM, h, hh, hl);
    }

    pool_kernel<<<B_, 512>>>(h, pooled);
    final_kernel<<<B_, 512>>>(pooled, lng, lnb, fcw, fcb, out);
}

// round 16
// speedup vs baseline: 2.7343x; 2.2768x over previous
#include <cuda_runtime.h>
#include <cuda_fp16.h>
#include <math.h>
#include <stdint.h>

#define B_     32
#define S_     512
#define DM     512
#define NH     8
#define NL     4
#define DFF    2048
#define FEAT   2048
#define NTOK   (B_ * S_)

// ---------------- scratch ----------------
__device__ float g_h   [NTOK * DM];
__device__ float g_tmp [NTOK * DM];
__device__ float g_pool[B_ * DM];
__device__ float g_bqkv[NL * 1536];

__device__ __half g_x16[NTOK * FEAT];     // x fp16; reused as ff fp16
__device__ __half g_h16[NTOK * DM];
__device__ __half g_c16[NTOK * DM];
__device__ __half g_q16[NTOK * DM];
__device__ __half g_k16[NTOK * DM];
__device__ __half g_v16[NTOK * DM];
#define WTOT 13631488
__device__ __half g_w16[WTOT];

#define LBASE   1048576
#define LSTRIDE 3145728

// ---------------- helpers ----------------
__device__ __forceinline__ uint32_t smem_u32(const void* p) {
    uint32_t a;
    asm("{ .reg .u64 t; cvta.to.shared.u64 t, %1; cvt.u32.u64 %0, t; }" : "=r"(a) : "l"(p));
    return a;
}
__device__ __forceinline__ void cp16(uint32_t s, const void* g) {
    asm volatile("cp.async.cg.shared.global [%0], [%1], 16;" :: "r"(s), "l"(g));
}
#define CP_COMMIT() asm volatile("cp.async.commit_group;" ::: "memory")

__device__ __forceinline__ void ldm4(uint32_t* r, uint32_t addr) {
    asm volatile("ldmatrix.sync.aligned.m8n8.x4.shared.b16 {%0,%1,%2,%3}, [%4];"
                 : "=r"(r[0]), "=r"(r[1]), "=r"(r[2]), "=r"(r[3]) : "r"(addr));
}
__device__ __forceinline__ void ldm4t(uint32_t* r, uint32_t addr) {
    asm volatile("ldmatrix.sync.aligned.m8n8.x4.trans.shared.b16 {%0,%1,%2,%3}, [%4];"
                 : "=r"(r[0]), "=r"(r[1]), "=r"(r[2]), "=r"(r[3]) : "r"(addr));
}
__device__ __forceinline__ void mma16816(float* c, const uint32_t* a, const uint32_t* b) {
    asm volatile(
        "mma.sync.aligned.m16n8k16.row.col.f32.f16.f16.f32 "
        "{%0,%1,%2,%3}, {%4,%5,%6,%7}, {%8,%9}, {%0,%1,%2,%3};"
        : "+f"(c[0]), "+f"(c[1]), "+f"(c[2]), "+f"(c[3])
        : "r"(a[0]), "r"(a[1]), "r"(a[2]), "r"(a[3]), "r"(b[0]), "r"(b[1]));
}
__device__ __forceinline__ uint32_t pack_h2(float a, float b) {
    __half2 h = __floats2half2_rn(a, b);
    return *(uint32_t*)&h;
}

// ---------------------------------------------------------------------------
// fp16 HMMA GEMM: C[M,N] = A[M,K] @ Bt[N,K]^T (+bias, epilogues)
// BM=BN=128, BK=32, 256 thr, 3-stage cp.async, 2 CTAs/SM.
// Stage: A 8KB | B 8KB = 16KB.
// EPI: 0 bias, 1 +relu, 2 +posenc, 3 +residual, 4 QKV-routed fp16 output.
// ---------------------------------------------------------------------------
#define GSTAGE 16384
#define GSMEM_TOTAL (3 * GSTAGE)

template<int EPI, bool WHALF, bool WF32>
__global__ __launch_bounds__(256, 2)
void gemm_mma(const __half* __restrict__ A, const __half* __restrict__ Bt,
              const float* __restrict__ bias, const float* __restrict__ res,
              float* __restrict__ Cf, __half* __restrict__ Ch,
              __half* __restrict__ Ch2, __half* __restrict__ Ch3,
              int N, int K)
{
    extern __shared__ char smem[];
    const uint32_t sb = smem_u32(smem);
    const int t = threadIdx.x, lane = t & 31, wid = t >> 5;
    const int wm = wid & 1, wn = wid >> 1;
    const int m0 = blockIdx.y << 7, n0 = blockIdx.x << 7;

    const int lr = t >> 1, lc0 = (t & 1) * 2;
    const int lsw = (lr & 6) >> 1;
    const char* gA = (const char*)(A  + (size_t)(m0 + lr) * K);
    const char* gB = (const char*)(Bt + (size_t)(n0 + lr) * K);

    auto load_stage = [&](int buf, int k0) {
        uint32_t base = sb + buf * GSTAGE;
#pragma unroll
        for (int c = lc0; c < lc0 + 2; c++) {
            uint32_t so = (uint32_t)(lr * 64 + ((c ^ lsw) << 4));
            size_t go = (size_t)(k0 + c * 8) * 2;
            cp16(base + so,        gA + go);
            cp16(base + 8192 + so, gB + go);
        }
        CP_COMMIT();
    };

    const int csa = (lane >> 4) & 1;
    const int csb = (lane >> 3) & 1;
    uint32_t offA[4], sA[4];
#pragma unroll
    for (int mi = 0; mi < 4; mi++) {
        int r = wm * 64 + mi * 16 + (lane & 15);
        offA[mi] = r * 64;
        sA[mi] = (r & 6) >> 1;
    }
    uint32_t offB[2], sB[2];
#pragma unroll
    for (int g = 0; g < 2; g++) {
        int r = wn * 32 + g * 16 + (lane & 7) + ((lane & 16) >> 1);
        offB[g] = r * 64;
        sB[g] = (r & 6) >> 1;
    }

    float acc[4][4][4];
#pragma unroll
    for (int i = 0; i < 4; i++)
#pragma unroll
        for (int j = 0; j < 4; j++)
#pragma unroll
            for (int e = 0; e < 4; e++) acc[i][j][e] = 0.0f;

    const int nst = K >> 5;
    load_stage(0, 0);
    load_stage(1, 32);

    int buf = 0;
    for (int st = 0; st < nst; st++) {
        if (st + 2 < nst) asm volatile("cp.async.wait_group 1;" ::: "memory");
        else              asm volatile("cp.async.wait_group 0;" ::: "memory");
        __syncthreads();
        if (st + 2 < nst) {
            int nb = buf + 2; if (nb >= 3) nb -= 3;
            load_stage(nb, (st + 2) * 32);
        }

        uint32_t base = sb + buf * GSTAGE;
#pragma unroll
        for (int ks = 0; ks < 2; ks++) {
            uint32_t ah[4][4];
#pragma unroll
            for (int mi = 0; mi < 4; mi++) {
                uint32_t ca = (((2 * ks + csa) ^ sA[mi]) << 4);
                ldm4(ah[mi], base + offA[mi] + ca);
            }
#pragma unroll
            for (int g = 0; g < 2; g++) {
                uint32_t cb = (((2 * ks + csb) ^ sB[g]) << 4);
                uint32_t rh[4];
                ldm4(rh, base + 8192 + offB[g] + cb);
#pragma unroll
                for (int mi = 0; mi < 4; mi++) {
                    mma16816(acc[mi][2*g],   ah[mi], &rh[0]);
                    mma16816(acc[mi][2*g+1], ah[mi], &rh[2]);
                }
            }
        }
        buf++; if (buf == 3) buf = 0;
    }

    // ---- epilogue ----
    const float kPE = (float)(-9.210340371976184 / 512.0);
    const int rbase = m0 + wm * 64 + (lane >> 2);
    const int cbase = n0 + wn * 32 + (lane & 3) * 2;
    __half* Oh = Ch;
    if (EPI == 4) {
        const int sel = n0 >> 9;
        Oh = (sel == 0) ? Ch : (sel == 1) ? Ch2 : Ch3;
    }
#pragma unroll
    for (int mi = 0; mi < 4; mi++) {
#pragma unroll
        for (int half_ = 0; half_ < 2; half_++) {
            const int row = rbase + mi * 16 + half_ * 8;
            const int s = row & (S_ - 1);
#pragma unroll
            for (int ni = 0; ni < 4; ni++) {
                const int col = cbase + ni * 8;
                const int ocol = (EPI == 4) ? (col & 511) : col;
                float vx = acc[mi][ni][2 * half_ + 0];
                float vy = acc[mi][ni][2 * half_ + 1];
                float2 bb = *(const float2*)(bias + col);
                vx += bb.x; vy += bb.y;
                if (EPI == 1) { vx = fmaxf(vx, 0.0f); vy = fmaxf(vy, 0.0f); }
                if (EPI == 2) {
                    float a = (float)s * expf((float)col * kPE);
                    vx += sinf(a); vy += cosf(a);
                }
                if (EPI == 3) {
                    float2 rr = *(const float2*)(res + (size_t)row * N + col);
                    vx += rr.x; vy += rr.y;
                }
                if (WF32)
                    *(float2*)(Cf + (size_t)row * N + ocol) = make_float2(vx, vy);
                if (WHALF)
                    *(uint32_t*)(Oh + (size_t)row * N + ocol) = pack_h2(vx, vy);
            }
        }
    }
}

// ---------------------------------------------------------------------------
// fp16 HMMA flash attention, K/V double-buffered.
// Smem tiles (stride 72 halfs = 144B): Q | buf0{K V} | buf1{K V} = 5 tiles.
// ---------------------------------------------------------------------------
#define AST 72
#define ATILE (64 * AST)
#define ATTN_SMEM (5 * ATILE * 2)   // 46080 B

__global__ __launch_bounds__(128)
void attn_mma(const __half* __restrict__ q, const __half* __restrict__ k,
              const __half* __restrict__ v, __half* __restrict__ ctx)
{
    extern __shared__ __half smh[];
    const uint32_t sq = smem_u32(smh);
    const int t = threadIdx.x, lane = t & 31, w = t >> 5;
    const int b = blockIdx.y >> 3, h = blockIdx.y & 7;
    const int hoff = h << 6;
    const size_t btok0 = (size_t)b * S_;
    const size_t qtok0 = btok0 + ((size_t)blockIdx.x << 6);

    const int lr = t >> 1, lc0 = (t & 1) * 4;

    auto load_kv = [&](int buf, int kt) {
        uint32_t kb = (1 + 2 * buf) * ATILE;
        size_t tok = btok0 + kt * 64 + lr;
        const __half* gk = k + tok * DM + hoff;
        const __half* gv = v + tok * DM + hoff;
#pragma unroll
        for (int c = lc0; c < lc0 + 4; c++) {
            cp16(sq + (kb         + lr * AST + c * 8) * 2, gk + c * 8);
            cp16(sq + (kb + ATILE + lr * AST + c * 8) * 2, gv + c * 8);
        }
        CP_COMMIT();
    };

    {
        const __half* gq = q + (qtok0 + lr) * DM + hoff;
#pragma unroll
        for (int c = lc0; c < lc0 + 4; c++)
            cp16(sq + (lr * AST + c * 8) * 2, gq + c * 8);
        CP_COMMIT();
    }
    load_kv(0, 0);

    float m1 = -INFINITY, m2 = -INFINITY, l1 = 0.0f, l2 = 0.0f;
    float o[8][4];
#pragma unroll
    for (int j = 0; j < 8; j++)
#pragma unroll
        for (int e = 0; e < 4; e++) o[j][e] = 0.0f;

    const uint32_t a_off = ((16 * w + (lane & 15)) * AST + ((lane >> 4) << 3)) * 2;
    const uint32_t k_row = (lane & 7) + ((lane & 16) >> 1);
    const uint32_t k_col = (((lane >> 3) & 1) << 3);
    const uint32_t v_off = ((lane & 15) * AST + ((lane >> 4) << 3)) * 2;

    for (int kt = 0; kt < 8; kt++) {
        const int buf = kt & 1;
        __syncthreads();
        if (kt + 1 < 8) {
            load_kv((kt + 1) & 1, kt + 1);
            asm volatile("cp.async.wait_group 1;" ::: "memory");
        } else {
            asm volatile("cp.async.wait_group 0;" ::: "memory");
        }
        __syncthreads();

        const uint32_t KH = (1 + 2 * buf) * ATILE;
        const uint32_t VH = KH + ATILE;

        float c_[8][4];
#pragma unroll
        for (int n = 0; n < 8; n++)
#pragma unroll
            for (int e = 0; e < 4; e++) c_[n][e] = 0.0f;

#pragma unroll
        for (int kc = 0; kc < 4; kc++) {
            uint32_t aq[4];
            ldm4(aq, sq + a_off + kc * 32);
#pragma unroll
            for (int g = 0; g < 4; g++) {
                uint32_t rh[4];
                uint32_t ko = ((g * 16 + k_row) * AST + kc * 16 + k_col) * 2;
                ldm4(rh, sq + KH * 2 + ko);
                mma16816(c_[2*g],   aq, &rh[0]);
                mma16816(c_[2*g+1], aq, &rh[2]);
            }
        }

        float mx1 = -INFINITY, mx2 = -INFINITY;
#pragma unroll
        for (int n = 0; n < 8; n++) {
#pragma unroll
            for (int e = 0; e < 4; e++) c_[n][e] *= 0.125f;
            mx1 = fmaxf(mx1, fmaxf(c_[n][0], c_[n][1]));
            mx2 = fmaxf(mx2, fmaxf(c_[n][2], c_[n][3]));
        }
#pragma unroll
        for (int off = 1; off < 4; off <<= 1) {
            mx1 = fmaxf(mx1, __shfl_xor_sync(0xffffffffu, mx1, off));
            mx2 = fmaxf(mx2, __shfl_xor_sync(0xffffffffu, mx2, off));
        }
        float mn1 = fmaxf(m1, mx1), mn2 = fmaxf(m2, mx2);
        float corr1 = __expf(m1 - mn1), corr2 = __expf(m2 - mn2);
        m1 = mn1; m2 = mn2;
        float s1 = 0.0f, s2 = 0.0f;
#pragma unroll
        for (int n = 0; n < 8; n++) {
            c_[n][0] = __expf(c_[n][0] - mn1);
            c_[n][1] = __expf(c_[n][1] - mn1);
            c_[n][2] = __expf(c_[n][2] - mn2);
            c_[n][3] = __expf(c_[n][3] - mn2);
            s1 += c_[n][0] + c_[n][1];
            s2 += c_[n][2] + c_[n][3];
        }
#pragma unroll
        for (int off = 1; off < 4; off <<= 1) {
            s1 += __shfl_xor_sync(0xffffffffu, s1, off);
            s2 += __shfl_xor_sync(0xffffffffu, s2, off);
        }
        l1 = l1 * corr1 + s1;
        l2 = l2 * corr2 + s2;
#pragma unroll
        for (int j = 0; j < 8; j++) {
            o[j][0] *= corr1; o[j][1] *= corr1;
            o[j][2] *= corr2; o[j][3] *= corr2;
        }

#pragma unroll
        for (int kc = 0; kc < 4; kc++) {
            uint32_t ph[4];
            ph[0] = pack_h2(c_[2*kc][0],   c_[2*kc][1]);
            ph[1] = pack_h2(c_[2*kc][2],   c_[2*kc][3]);
            ph[2] = pack_h2(c_[2*kc+1][0], c_[2*kc+1][1]);
            ph[3] = pack_h2(c_[2*kc+1][2], c_[2*kc+1][3]);
#pragma unroll
            for (int j = 0; j < 4; j++) {
                uint32_t rv[4];
                uint32_t vo = (kc * 16 * AST + j * 16) * 2 + v_off;
                ldm4t(rv, sq + VH * 2 + vo);
                mma16816(o[2*j],   ph, &rv[0]);
                mma16816(o[2*j+1], ph, &rv[2]);
            }
        }
    }

    float inv1 = 1.0f / l1, inv2 = 1.0f / l2;
    const size_t row1 = qtok0 + 16 * w + (lane >> 2);
    const size_t row2 = row1 + 8;
    const int col = hoff + (lane & 3) * 2;
#pragma unroll
    for (int j = 0; j < 8; j++) {
        *(uint32_t*)(ctx + row1 * DM + col + j * 8) = pack_h2(o[j][0] * inv1, o[j][1] * inv1);
        *(uint32_t*)(ctx + row2 * DM + col + j * 8) = pack_h2(o[j][2] * inv2, o[j][3] * inv2);
    }
}

// ---------------------------------------------------------------------------
// Transpose + fp16 convert helpers
// ---------------------------------------------------------------------------
__device__ __forceinline__ void wsplit_tile(const float* W, __half* Th,
                                            int K, int N, int n0, int k0)
{
    __shared__ float ts[32][33];
    int tx = threadIdx.x & 31, ty = threadIdx.x >> 5;
#pragma unroll
    for (int i = 0; i < 4; i++)
        ts[ty + i * 8][tx] = W[(size_t)(k0 + ty + i * 8) * N + n0 + tx];
    __syncthreads();
#pragma unroll
    for (int i = 0; i < 4; i++)
        Th[(size_t)(n0 + ty + i * 8) * K + k0 + tx] = __float2half(ts[tx][ty + i * 8]);
}

__global__ __launch_bounds__(256)
void wsplit_qkvo(const float* __restrict__ Wq, const float* __restrict__ Wk,
                 const float* __restrict__ Wv, const float* __restrict__ Wo,
                 __half* __restrict__ Th,
                 const float* __restrict__ bq, const float* __restrict__ bk,
                 const float* __restrict__ bv, float* __restrict__ bqkv)
{
    int z = blockIdx.z;
    if (z == 16) {
        int idx = blockIdx.y * 16 + blockIdx.x;
        if (idx < 24) {
            int l = idx / 6, i = (idx % 6) * 256 + threadIdx.x;
            float v = (i < 512) ? bq[l * 512 + i]
                    : (i < 1024) ? bk[l * 512 + i - 512]
                    : bv[l * 512 + i - 1024];
            bqkv[l * 1536 + i] = v;
        }
        return;
    }
    int l = z >> 2, tp = z & 3;
    const float* W = ((tp == 0) ? Wq : (tp == 1) ? Wk : (tp == 2) ? Wv : Wo)
                   + (size_t)l * DM * DM;
    size_t doff = (size_t)l * LSTRIDE + (size_t)tp * 262144;
    wsplit_tile(W, Th + doff, DM, DM, blockIdx.x * 32, blockIdx.y * 32);
}

__global__ __launch_bounds__(256)
void wsplit_t(const float* __restrict__ W, __half* __restrict__ Th,
              int K, int N, size_t src_lstride, size_t dst_lstride)
{
    int l = blockIdx.z;
    wsplit_tile(W + (size_t)l * src_lstride, Th + (size_t)l * dst_lstride,
                K, N, blockIdx.x * 32, blockIdx.y * 32);
}

__global__ __launch_bounds__(256)
void wsplit_w2x(const float* __restrict__ W2, __half* __restrict__ Th,
                const float* __restrict__ x, __half* __restrict__ x16)
{
    int z = blockIdx.z;
    if (z < 4) {
        wsplit_tile(W2 + (size_t)z * DFF * DM, Th + (size_t)z * LSTRIDE,
                    DFF, DM, blockIdx.x * 32, blockIdx.y * 32);
        return;
    }
    size_t lin = (((size_t)(z - 4) * 1024 + blockIdx.y * 16 + blockIdx.x) * 256
                  + threadIdx.x) * 4;
    float4 val = *(const float4*)(x + lin);
    *(uint2*)(x16 + lin) = make_uint2(pack_h2(val.x, val.y), pack_h2(val.z, val.w));
}

// ---------------------------------------------------------------------------
// LN: warp-per-row, fp32 out + fp16 out
// ---------------------------------------------------------------------------
__global__ __launch_bounds__(256)
void ln_kernel(const float* __restrict__ in, const float* __restrict__ g,
               const float* __restrict__ bb, float* __restrict__ out,
               __half* __restrict__ oh)
{
    int w = threadIdx.x >> 5, lane = threadIdx.x & 31;
    size_t row = (size_t)blockIdx.x * 8 + w;
    float4 v[4];
    float sum = 0.0f;
#pragma unroll
    for (int j = 0; j < 4; j++) {
        v[j] = *(const float4*)&in[row * DM + j * 128 + lane * 4];
        sum += v[j].x + v[j].y + v[j].z + v[j].w;
    }
#pragma unroll
    for (int off = 16; off > 0; off >>= 1)
        sum += __shfl_xor_sync(0xffffffffu, sum, off);
    float mu = sum * (1.0f / DM);
    float vs = 0.0f;
#pragma unroll
    for (int j = 0; j < 4; j++) {
        v[j].x -= mu; v[j].y -= mu; v[j].z -= mu; v[j].w -= mu;
        vs += v[j].x * v[j].x + v[j].y * v[j].y + v[j].z * v[j].z + v[j].w * v[j].w;
    }
#pragma unroll
    for (int off = 16; off > 0; off >>= 1)
        vs += __shfl_xor_sync(0xffffffffu, vs, off);
    float rstd = rsqrtf(vs * (1.0f / DM) + 1e-5f);
#pragma unroll
    for (int j = 0; j < 4; j++) {
        int c = j * 128 + lane * 4;
        float4 gv = *(const float4*)&g[c];
        float4 bv = *(const float4*)&bb[c];
        float4 o;
        o.x = v[j].x * rstd * gv.x + bv.x;
        o.y = v[j].y * rstd * gv.y + bv.y;
        o.z = v[j].z * rstd * gv.z + bv.z;
        o.w = v[j].w * rstd * gv.w + bv.w;
        *(float4*)&out[row * DM + c] = o;
        *(uint2*)&oh[row * DM + c] = make_uint2(pack_h2(o.x, o.y), pack_h2(o.z, o.w));
    }
}

// ---------------------------------------------------------------------------
// pool / head
// ---------------------------------------------------------------------------
__device__ __forceinline__ float block_sum(float v, float* red, int nwarps)
{
    int lane = threadIdx.x & 31, w = threadIdx.x >> 5;
#pragma unroll
    for (int off = 16; off > 0; off >>= 1)
        v += __shfl_xor_sync(0xffffffffu, v, off);
    if (lane == 0) red[w] = v;
    __syncthreads();
    if (w == 0) {
        float ts = (lane < nwarps) ? red[lane] : 0.0f;
#pragma unroll
        for (int off = 16; off > 0; off >>= 1)
            ts += __shfl_xor_sync(0xffffffffu, ts, off);
        if (lane == 0) red[0] = ts;
    }
    __syncthreads();
    float r = red[0];
    __syncthreads();
    return r;
}

__global__ __launch_bounds__(512)
void pool_kernel(const float* __restrict__ h, float* __restrict__ pooled)
{
    int b = blockIdx.x, d = threadIdx.x;
    const float* p = h + (size_t)b * S_ * DM + d;
    float s = 0.0f;
#pragma unroll 8
    for (int i = 0; i < S_; i++) s += p[(size_t)i * DM];
    pooled[b * DM + d] = s * (1.0f / S_);
}

__global__ __launch_bounds__(512)
void final_kernel(const float* __restrict__ pooled, const float* __restrict__ lng,
                  const float* __restrict__ lnb, const float* __restrict__ fcw,
                  const float* __restrict__ fcb, float* __restrict__ out)
{
    __shared__ float red[32];
    int b = blockIdx.x, d = threadIdx.x;
    float x = pooled[b * DM + d];
    float mu = block_sum(x, red, 16) * (1.0f / DM);
    float dx = x - mu;
    float var = block_sum(dx * dx, red, 16) * (1.0f / DM);
    float y = dx * rsqrtf(var + 1e-5f) * lng[d] + lnb[d];
    float z = block_sum(y * fcw[d], red, 16);
    if (d == 0) out[b] = 1.0f / (1.0f + expf(-(z + fcb[0])));
}

// ---------------------------------------------------------------------------
// launch
// ---------------------------------------------------------------------------
extern "C" void kernel_launch(void* const* d_in, const int* in_sizes, int n_in,
                              void* d_out, int out_size)
{
    const float* x    = (const float*)d_in[0];
    const float* Wp   = (const float*)d_in[1];
    const float* bp   = (const float*)d_in[2];
    const float* Wq   = (const float*)d_in[3];
    const float* bq   = (const float*)d_in[4];
    const float* Wk   = (const float*)d_in[5];
    const float* bk   = (const float*)d_in[6];
    const float* Wv   = (const float*)d_in[7];
    const float* bv   = (const float*)d_in[8];
    const float* Wo   = (const float*)d_in[9];
    const float* bo   = (const float*)d_in[10];
    const float* ln1g = (const float*)d_in[11];
    const float* ln1b = (const float*)d_in[12];
    const float* W1   = (const float*)d_in[13];
    const float* b1   = (const float*)d_in[14];
    const float* W2   = (const float*)d_in[15];
    const float* b2   = (const float*)d_in[16];
    const float* ln2g = (const float*)d_in[17];
    const float* ln2b = (const float*)d_in[18];
    const float* lng  = (const float*)d_in[19];
    const float* lnb  = (const float*)d_in[20];
    const float* fcw  = (const float*)d_in[21];
    const float* fcb  = (const float*)d_in[22];
    float* out = (float*)d_out;

    float *h, *tmp, *pooled, *bqkv;
    __half *x16, *h16, *c16, *q16, *k16, *v16, *w16;
    cudaGetSymbolAddress((void**)&h, g_h);
    cudaGetSymbolAddress((void**)&tmp, g_tmp);
    cudaGetSymbolAddress((void**)&pooled, g_pool);
    cudaGetSymbolAddress((void**)&bqkv, g_bqkv);
    cudaGetSymbolAddress((void**)&x16, g_x16);
    cudaGetSymbolAddress((void**)&h16, g_h16);
    cudaGetSymbolAddress((void**)&c16, g_c16);
    cudaGetSymbolAddress((void**)&q16, g_q16);
    cudaGetSymbolAddress((void**)&k16, g_k16);
    cudaGetSymbolAddress((void**)&v16, g_v16);
    cudaGetSymbolAddress((void**)&w16, g_w16);

    cudaFuncSetAttribute(gemm_mma<2,true,true>,  cudaFuncAttributeMaxDynamicSharedMemorySize, GSMEM_TOTAL);
    cudaFuncSetAttribute(gemm_mma<4,true,false>, cudaFuncAttributeMaxDynamicSharedMemorySize, GSMEM_TOTAL);
    cudaFuncSetAttribute(gemm_mma<3,false,true>, cudaFuncAttributeMaxDynamicSharedMemorySize, GSMEM_TOTAL);
    cudaFuncSetAttribute(gemm_mma<1,true,false>, cudaFuncAttributeMaxDynamicSharedMemorySize, GSMEM_TOTAL);
    cudaFuncSetAttribute(attn_mma, cudaFuncAttributeMaxDynamicSharedMemorySize, ATTN_SMEM);

    // ---- preprocessing: 4 launches ----
    wsplit_qkvo<<<dim3(16,16,17), 256>>>(Wq, Wk, Wv, Wo, w16+LBASE, bq, bk, bv, bqkv);
    wsplit_t<<<dim3(16,64,1), 256>>>(Wp, w16, FEAT, DM, 0, 0);
    wsplit_t<<<dim3(64,16,NL), 256>>>(W1, w16+LBASE+1048576, DM, DFF,
                                      (size_t)DM*DFF, LSTRIDE);
    wsplit_w2x<<<dim3(16,64,36), 256>>>(W2, w16+LBASE+2097152, x, x16);

    dim3 gDM(DM / 128, NTOK / 128);
    dim3 gQKV(1536 / 128, NTOK / 128);
    dim3 gFF(DFF / 128, NTOK / 128);
    dim3 gAtt(S_ / 64, B_ * NH);

    gemm_mma<2,true,true><<<gDM, 256, GSMEM_TOTAL>>>(
        x16, w16, bp, nullptr, h, h16, nullptr, nullptr, DM, FEAT);

    for (int l = 0; l < NL; l++) {
        size_t b0 = LBASE + (size_t)l * LSTRIDE;
        gemm_mma<4,true,false><<<gQKV, 256, GSMEM_TOTAL>>>(
            h16, w16+b0, bqkv + l*1536, nullptr, nullptr,
            q16, k16, v16, DM, DM);

        attn_mma<<<gAtt, 128, ATTN_SMEM>>>(q16, k16, v16, c16);

        gemm_mma<3,false,true><<<gDM, 256, GSMEM_TOTAL>>>(
            c16, w16+b0+786432, bo + l*DM, h, tmp, nullptr, nullptr, nullptr, DM, DM);
        ln_kernel<<<NTOK/8, 256>>>(tmp, ln1g + l*DM, ln1b + l*DM, h, h16);

        gemm_mma<1,true,false><<<gFF, 256, GSMEM_TOTAL>>>(
            h16, w16+b0+1048576, b1 + l*DFF, nullptr, nullptr,
            x16, nullptr, nullptr, DFF, DM);
        gemm_mma<3,false,true><<<gDM, 256, GSMEM_TOTAL>>>(
            x16, w16+b0+2097152, b2 + l*DM, h, tmp, nullptr, nullptr, nullptr, DM, DFF);
        ln_kernel<<<NTOK/8, 256>>>(tmp, ln2g + l*DM, ln2b + l*DM, h, h16);
    }

    pool_kernel<<<B_, 512>>>(h, pooled);
    final_kernel<<<B_, 512>>>(pooled, lng, lnb, fcw, fcb, out);
}

// round 17
// speedup vs baseline: 2.8139x; 1.0291x over previous
#include <cuda_runtime.h>
#include <cuda_fp16.h>
#include <math.h>
#include <stdint.h>

#define B_     32
#define S_     512
#define DM     512
#define NH     8
#define NL     4
#define DFF    2048
#define FEAT   2048
#define NTOK   (B_ * S_)

// ---------------- scratch ----------------
__device__ float g_h   [NTOK * DM];
__device__ float g_tmp [NTOK * DM];
__device__ float g_pool[B_ * DM];
__device__ float g_bqkv[NL * 1536];

__device__ __half g_x16[NTOK * FEAT];
__device__ __half g_h16[NTOK * DM];
__device__ __half g_c16[NTOK * DM];
__device__ __half g_q16[NTOK * DM];
__device__ __half g_k16[NTOK * DM];
__device__ __half g_v16[NTOK * DM];
#define WTOT 13631488
__device__ __half g_w16[WTOT];

#define LBASE   1048576
#define LSTRIDE 3145728

// ---------------- helpers ----------------
__device__ __forceinline__ uint32_t smem_u32(const void* p) {
    uint32_t a;
    asm("{ .reg .u64 t; cvta.to.shared.u64 t, %1; cvt.u32.u64 %0, t; }" : "=r"(a) : "l"(p));
    return a;
}
__device__ __forceinline__ void cp16(uint32_t s, const void* g) {
    asm volatile("cp.async.cg.shared.global [%0], [%1], 16;" :: "r"(s), "l"(g));
}
#define CP_COMMIT() asm volatile("cp.async.commit_group;" ::: "memory")

__device__ __forceinline__ void ldm4(uint32_t* r, uint32_t addr) {
    asm volatile("ldmatrix.sync.aligned.m8n8.x4.shared.b16 {%0,%1,%2,%3}, [%4];"
                 : "=r"(r[0]), "=r"(r[1]), "=r"(r[2]), "=r"(r[3]) : "r"(addr));
}
__device__ __forceinline__ void ldm4t(uint32_t* r, uint32_t addr) {
    asm volatile("ldmatrix.sync.aligned.m8n8.x4.trans.shared.b16 {%0,%1,%2,%3}, [%4];"
                 : "=r"(r[0]), "=r"(r[1]), "=r"(r[2]), "=r"(r[3]) : "r"(addr));
}
__device__ __forceinline__ void mma16816(float* c, const uint32_t* a, const uint32_t* b) {
    asm volatile(
        "mma.sync.aligned.m16n8k16.row.col.f32.f16.f16.f32 "
        "{%0,%1,%2,%3}, {%4,%5,%6,%7}, {%8,%9}, {%0,%1,%2,%3};"
        : "+f"(c[0]), "+f"(c[1]), "+f"(c[2]), "+f"(c[3])
        : "r"(a[0]), "r"(a[1]), "r"(a[2]), "r"(a[3]), "r"(b[0]), "r"(b[1]));
}
__device__ __forceinline__ uint32_t pack_h2(float a, float b) {
    __half2 h = __floats2half2_rn(a, b);
    return *(uint32_t*)&h;
}

// ---------------------------------------------------------------------------
// fp16 HMMA GEMM: C[M,N] = A[M,K] @ Bt[N,K]^T (+bias, epilogues)
// BM=BN=128, BK=64, 256 thr, 3-stage cp.async, 2 CTAs/SM.
// Stage 32KB: A[128x64] 16KB | B[128x64] 16KB; 128B rows, 8-chunk XOR swizzle.
// EPI: 0 bias, 1 +relu, 2 +posenc, 3 +residual, 4 QKV-routed fp16 output.
// ---------------------------------------------------------------------------
#define GSTAGE 32768
#define GSMEM_TOTAL (3 * GSTAGE)

template<int EPI, bool WHALF, bool WF32>
__global__ __launch_bounds__(256, 2)
void gemm_mma(const __half* __restrict__ A, const __half* __restrict__ Bt,
              const float* __restrict__ bias, const float* __restrict__ res,
              float* __restrict__ Cf, __half* __restrict__ Ch,
              __half* __restrict__ Ch2, __half* __restrict__ Ch3,
              int N, int K)
{
    extern __shared__ char smem[];
    const uint32_t sb = smem_u32(smem);
    const int t = threadIdx.x, lane = t & 31, wid = t >> 5;
    const int wm = wid & 1, wn = wid >> 1;
    const int m0 = blockIdx.y << 7, n0 = blockIdx.x << 7;

    const int lr = t >> 1, lc0 = (t & 1) * 4;
    const int lsw = lr & 7;
    const char* gA = (const char*)(A  + (size_t)(m0 + lr) * K);
    const char* gB = (const char*)(Bt + (size_t)(n0 + lr) * K);

    auto load_stage = [&](int buf, int k0) {
        uint32_t base = sb + buf * GSTAGE;
#pragma unroll
        for (int c = lc0; c < lc0 + 4; c++) {
            uint32_t so = (uint32_t)(lr * 128 + ((c ^ lsw) << 4));
            size_t go = (size_t)(k0 + c * 8) * 2;
            cp16(base + so,         gA + go);
            cp16(base + 16384 + so, gB + go);
        }
        CP_COMMIT();
    };

    const int csa = (lane >> 4) & 1;
    const int csb = (lane >> 3) & 1;
    uint32_t offA[4], sA[4];
#pragma unroll
    for (int mi = 0; mi < 4; mi++) {
        int r = wm * 64 + mi * 16 + (lane & 15);
        offA[mi] = r * 128;
        sA[mi] = r & 7;
    }
    uint32_t offB[2], sB[2];
#pragma unroll
    for (int g = 0; g < 2; g++) {
        int r = wn * 32 + g * 16 + (lane & 7) + ((lane & 16) >> 1);
        offB[g] = r * 128;
        sB[g] = r & 7;
    }

    float acc[4][4][4];
#pragma unroll
    for (int i = 0; i < 4; i++)
#pragma unroll
        for (int j = 0; j < 4; j++)
#pragma unroll
            for (int e = 0; e < 4; e++) acc[i][j][e] = 0.0f;

    const int nst = K >> 6;
    load_stage(0, 0);
    load_stage(1, 64);

    int buf = 0;
    for (int st = 0; st < nst; st++) {
        if (st + 2 < nst) asm volatile("cp.async.wait_group 1;" ::: "memory");
        else              asm volatile("cp.async.wait_group 0;" ::: "memory");
        __syncthreads();
        if (st + 2 < nst) {
            int nb = buf + 2; if (nb >= 3) nb -= 3;
            load_stage(nb, (st + 2) * 64);
        }

        uint32_t base = sb + buf * GSTAGE;
#pragma unroll
        for (int kb = 0; kb < 4; kb++) {
            uint32_t ah[4][4];
#pragma unroll
            for (int mi = 0; mi < 4; mi++)
                ldm4(ah[mi], base + offA[mi] + (((2 * kb + csa) ^ sA[mi]) << 4));
#pragma unroll
            for (int g = 0; g < 2; g++) {
                uint32_t rh[4];
                ldm4(rh, base + 16384 + offB[g] + (((2 * kb + csb) ^ sB[g]) << 4));
#pragma unroll
                for (int mi = 0; mi < 4; mi++) {
                    mma16816(acc[mi][2*g],   ah[mi], &rh[0]);
                    mma16816(acc[mi][2*g+1], ah[mi], &rh[2]);
                }
            }
        }
        buf++; if (buf == 3) buf = 0;
    }

    // ---- epilogue ----
    const float kPE = (float)(-9.210340371976184 / 512.0);
    const int rbase = m0 + wm * 64 + (lane >> 2);
    const int cbase = n0 + wn * 32 + (lane & 3) * 2;
    __half* Oh = Ch;
    if (EPI == 4) {
        const int sel = n0 >> 9;
        Oh = (sel == 0) ? Ch : (sel == 1) ? Ch2 : Ch3;
    }
#pragma unroll
    for (int mi = 0; mi < 4; mi++) {
#pragma unroll
        for (int half_ = 0; half_ < 2; half_++) {
            const int row = rbase + mi * 16 + half_ * 8;
            const int s = row & (S_ - 1);
#pragma unroll
            for (int ni = 0; ni < 4; ni++) {
                const int col = cbase + ni * 8;
                const int ocol = (EPI == 4) ? (col & 511) : col;
                float vx = acc[mi][ni][2 * half_ + 0];
                float vy = acc[mi][ni][2 * half_ + 1];
                float2 bb = *(const float2*)(bias + col);
                vx += bb.x; vy += bb.y;
                if (EPI == 1) { vx = fmaxf(vx, 0.0f); vy = fmaxf(vy, 0.0f); }
                if (EPI == 2) {
                    float a = (float)s * expf((float)col * kPE);
                    vx += sinf(a); vy += cosf(a);
                }
                if (EPI == 3) {
                    float2 rr = *(const float2*)(res + (size_t)row * N + col);
                    vx += rr.x; vy += rr.y;
                }
                if (WF32)
                    *(float2*)(Cf + (size_t)row * N + ocol) = make_float2(vx, vy);
                if (WHALF)
                    *(uint32_t*)(Oh + (size_t)row * N + ocol) = pack_h2(vx, vy);
            }
        }
    }
}

// ---------------------------------------------------------------------------
// fp16 HMMA flash attention: 128-row q-tile, 256 thr (8 warps x 16 rows),
// K/V double-buffered 64-token tiles.
// Smem: Q[128x72] | buf0{K V} | buf1{K V}  (54KB)
// ---------------------------------------------------------------------------
#define AST 72
#define QTILE (128 * AST)
#define KVTILE (64 * AST)
#define ATTN_SMEM ((QTILE + 4 * KVTILE) * 2)   // 55296 B

__global__ __launch_bounds__(256)
void attn_mma(const __half* __restrict__ q, const __half* __restrict__ k,
              const __half* __restrict__ v, __half* __restrict__ ctx)
{
    extern __shared__ __half smh[];
    const uint32_t sq = smem_u32(smh);
    const int t = threadIdx.x, lane = t & 31, w = t >> 5;
    const int b = blockIdx.y >> 3, h = blockIdx.y & 7;
    const int hoff = h << 6;
    const size_t btok0 = (size_t)b * S_;
    const size_t qtok0 = btok0 + ((size_t)blockIdx.x << 7);

    // Q loader: 2 thr/row, 4 chunks each
    const int qlr = t >> 1, qlc0 = (t & 1) * 4;
    // KV loader: 4 thr/row, 2 chunks each
    const int klr = t >> 2, klc0 = (t & 3) * 2;

    auto load_kv = [&](int buf, int kt) {
        uint32_t kb = QTILE + buf * 2 * KVTILE;
        size_t tok = btok0 + kt * 64 + klr;
        const __half* gk = k + tok * DM + hoff;
        const __half* gv = v + tok * DM + hoff;
#pragma unroll
        for (int c = klc0; c < klc0 + 2; c++) {
            cp16(sq + (kb          + klr * AST + c * 8) * 2, gk + c * 8);
            cp16(sq + (kb + KVTILE + klr * AST + c * 8) * 2, gv + c * 8);
        }
        CP_COMMIT();
    };

    {
        const __half* gq = q + (qtok0 + qlr) * DM + hoff;
#pragma unroll
        for (int c = qlc0; c < qlc0 + 4; c++)
            cp16(sq + (qlr * AST + c * 8) * 2, gq + c * 8);
        CP_COMMIT();
    }
    load_kv(0, 0);

    float m1 = -INFINITY, m2 = -INFINITY, l1 = 0.0f, l2 = 0.0f;
    float o[8][4];
#pragma unroll
    for (int j = 0; j < 8; j++)
#pragma unroll
        for (int e = 0; e < 4; e++) o[j][e] = 0.0f;

    const uint32_t a_off = ((16 * w + (lane & 15)) * AST + ((lane >> 4) << 3)) * 2;
    const uint32_t k_row = (lane & 7) + ((lane & 16) >> 1);
    const uint32_t k_col = (((lane >> 3) & 1) << 3);
    const uint32_t v_off = ((lane & 15) * AST + ((lane >> 4) << 3)) * 2;

    for (int kt = 0; kt < 8; kt++) {
        const int buf = kt & 1;
        __syncthreads();
        if (kt + 1 < 8) {
            load_kv((kt + 1) & 1, kt + 1);
            asm volatile("cp.async.wait_group 1;" ::: "memory");
        } else {
            asm volatile("cp.async.wait_group 0;" ::: "memory");
        }
        __syncthreads();

        const uint32_t KH = QTILE + buf * 2 * KVTILE;
        const uint32_t VH = KH + KVTILE;

        float c_[8][4];
#pragma unroll
        for (int n = 0; n < 8; n++)
#pragma unroll
            for (int e = 0; e < 4; e++) c_[n][e] = 0.0f;

#pragma unroll
        for (int kc = 0; kc < 4; kc++) {
            uint32_t aq[4];
            ldm4(aq, sq + a_off + kc * 32);
#pragma unroll
            for (int g = 0; g < 4; g++) {
                uint32_t rh[4];
                uint32_t ko = ((g * 16 + k_row) * AST + kc * 16 + k_col) * 2;
                ldm4(rh, sq + KH * 2 + ko);
                mma16816(c_[2*g],   aq, &rh[0]);
                mma16816(c_[2*g+1], aq, &rh[2]);
            }
        }

        float mx1 = -INFINITY, mx2 = -INFINITY;
#pragma unroll
        for (int n = 0; n < 8; n++) {
#pragma unroll
            for (int e = 0; e < 4; e++) c_[n][e] *= 0.125f;
            mx1 = fmaxf(mx1, fmaxf(c_[n][0], c_[n][1]));
            mx2 = fmaxf(mx2, fmaxf(c_[n][2], c_[n][3]));
        }
#pragma unroll
        for (int off = 1; off < 4; off <<= 1) {
            mx1 = fmaxf(mx1, __shfl_xor_sync(0xffffffffu, mx1, off));
            mx2 = fmaxf(mx2, __shfl_xor_sync(0xffffffffu, mx2, off));
        }
        float mn1 = fmaxf(m1, mx1), mn2 = fmaxf(m2, mx2);
        float corr1 = __expf(m1 - mn1), corr2 = __expf(m2 - mn2);
        m1 = mn1; m2 = mn2;
        float s1 = 0.0f, s2 = 0.0f;
#pragma unroll
        for (int n = 0; n < 8; n++) {
            c_[n][0] = __expf(c_[n][0] - mn1);
            c_[n][1] = __expf(c_[n][1] - mn1);
            c_[n][2] = __expf(c_[n][2] - mn2);
            c_[n][3] = __expf(c_[n][3] - mn2);
            s1 += c_[n][0] + c_[n][1];
            s2 += c_[n][2] + c_[n][3];
        }
#pragma unroll
        for (int off = 1; off < 4; off <<= 1) {
            s1 += __shfl_xor_sync(0xffffffffu, s1, off);
            s2 += __shfl_xor_sync(0xffffffffu, s2, off);
        }
        l1 = l1 * corr1 + s1;
        l2 = l2 * corr2 + s2;
#pragma unroll
        for (int j = 0; j < 8; j++) {
            o[j][0] *= corr1; o[j][1] *= corr1;
            o[j][2] *= corr2; o[j][3] *= corr2;
        }

#pragma unroll
        for (int kc = 0; kc < 4; kc++) {
            uint32_t ph[4];
            ph[0] = pack_h2(c_[2*kc][0],   c_[2*kc][1]);
            ph[1] = pack_h2(c_[2*kc][2],   c_[2*kc][3]);
            ph[2] = pack_h2(c_[2*kc+1][0], c_[2*kc+1][1]);
            ph[3] = pack_h2(c_[2*kc+1][2], c_[2*kc+1][3]);
#pragma unroll
            for (int j = 0; j < 4; j++) {
                uint32_t rv[4];
                uint32_t vo = (kc * 16 * AST + j * 16) * 2 + v_off;
                ldm4t(rv, sq + VH * 2 + vo);
                mma16816(o[2*j],   ph, &rv[0]);
                mma16816(o[2*j+1], ph, &rv[2]);
            }
        }
    }

    float inv1 = 1.0f / l1, inv2 = 1.0f / l2;
    const size_t row1 = qtok0 + 16 * w + (lane >> 2);
    const size_t row2 = row1 + 8;
    const int col = hoff + (lane & 3) * 2;
#pragma unroll
    for (int j = 0; j < 8; j++) {
        *(uint32_t*)(ctx + row1 * DM + col + j * 8) = pack_h2(o[j][0] * inv1, o[j][1] * inv1);
        *(uint32_t*)(ctx + row2 * DM + col + j * 8) = pack_h2(o[j][2] * inv2, o[j][3] * inv2);
    }
}

// ---------------------------------------------------------------------------
// Transpose + fp16 convert helpers
// ---------------------------------------------------------------------------
__device__ __forceinline__ void wsplit_tile(const float* W, __half* Th,
                                            int K, int N, int n0, int k0)
{
    __shared__ float ts[32][33];
    int tx = threadIdx.x & 31, ty = threadIdx.x >> 5;
#pragma unroll
    for (int i = 0; i < 4; i++)
        ts[ty + i * 8][tx] = W[(size_t)(k0 + ty + i * 8) * N + n0 + tx];
    __syncthreads();
#pragma unroll
    for (int i = 0; i < 4; i++)
        Th[(size_t)(n0 + ty + i * 8) * K + k0 + tx] = __float2half(ts[tx][ty + i * 8]);
}

__global__ __launch_bounds__(256)
void wsplit_qkvo(const float* __restrict__ Wq, const float* __restrict__ Wk,
                 const float* __restrict__ Wv, const float* __restrict__ Wo,
                 __half* __restrict__ Th,
                 const float* __restrict__ bq, const float* __restrict__ bk,
                 const float* __restrict__ bv, float* __restrict__ bqkv)
{
    int z = blockIdx.z;
    if (z == 16) {
        int idx = blockIdx.y * 16 + blockIdx.x;
        if (idx < 24) {
            int l = idx / 6, i = (idx % 6) * 256 + threadIdx.x;
            float v = (i < 512) ? bq[l * 512 + i]
                    : (i < 1024) ? bk[l * 512 + i - 512]
                    : bv[l * 512 + i - 1024];
            bqkv[l * 1536 + i] = v;
        }
        return;
    }
    int l = z >> 2, tp = z & 3;
    const float* W = ((tp == 0) ? Wq : (tp == 1) ? Wk : (tp == 2) ? Wv : Wo)
                   + (size_t)l * DM * DM;
    size_t doff = (size_t)l * LSTRIDE + (size_t)tp * 262144;
    wsplit_tile(W, Th + doff, DM, DM, blockIdx.x * 32, blockIdx.y * 32);
}

__global__ __launch_bounds__(256)
void wsplit_t(const float* __restrict__ W, __half* __restrict__ Th,
              int K, int N, size_t src_lstride, size_t dst_lstride)
{
    int l = blockIdx.z;
    wsplit_tile(W + (size_t)l * src_lstride, Th + (size_t)l * dst_lstride,
                K, N, blockIdx.x * 32, blockIdx.y * 32);
}

__global__ __launch_bounds__(256)
void wsplit_w2x(const float* __restrict__ W2, __half* __restrict__ Th,
                const float* __restrict__ x, __half* __restrict__ x16)
{
    int z = blockIdx.z;
    if (z < 4) {
        wsplit_tile(W2 + (size_t)z * DFF * DM, Th + (size_t)z * LSTRIDE,
                    DFF, DM, blockIdx.x * 32, blockIdx.y * 32);
        return;
    }
    size_t lin = (((size_t)(z - 4) * 1024 + blockIdx.y * 16 + blockIdx.x) * 256
                  + threadIdx.x) * 4;
    float4 val = *(const float4*)(x + lin);
    *(uint2*)(x16 + lin) = make_uint2(pack_h2(val.x, val.y), pack_h2(val.z, val.w));
}

// ---------------------------------------------------------------------------
// LN: warp-per-row, fp32 out + fp16 out
// ---------------------------------------------------------------------------
__global__ __launch_bounds__(256)
void ln_kernel(const float* __restrict__ in, const float* __restrict__ g,
               const float* __restrict__ bb, float* __restrict__ out,
               __half* __restrict__ oh)
{
    int w = threadIdx.x >> 5, lane = threadIdx.x & 31;
    size_t row = (size_t)blockIdx.x * 8 + w;
    float4 v[4];
    float sum = 0.0f;
#pragma unroll
    for (int j = 0; j < 4; j++) {
        v[j] = *(const float4*)&in[row * DM + j * 128 + lane * 4];
        sum += v[j].x + v[j].y + v[j].z + v[j].w;
    }
#pragma unroll
    for (int off = 16; off > 0; off >>= 1)
        sum += __shfl_xor_sync(0xffffffffu, sum, off);
    float mu = sum * (1.0f / DM);
    float vs = 0.0f;
#pragma unroll
    for (int j = 0; j < 4; j++) {
        v[j].x -= mu; v[j].y -= mu; v[j].z -= mu; v[j].w -= mu;
        vs += v[j].x * v[j].x + v[j].y * v[j].y + v[j].z * v[j].z + v[j].w * v[j].w;
    }
#pragma unroll
    for (int off = 16; off > 0; off >>= 1)
        vs += __shfl_xor_sync(0xffffffffu, vs, off);
    float rstd = rsqrtf(vs * (1.0f / DM) + 1e-5f);
#pragma unroll
    for (int j = 0; j < 4; j++) {
        int c = j * 128 + lane * 4;
        float4 gv = *(const float4*)&g[c];
        float4 bv = *(const float4*)&bb[c];
        float4 o;
        o.x = v[j].x * rstd * gv.x + bv.x;
        o.y = v[j].y * rstd * gv.y + bv.y;
        o.z = v[j].z * rstd * gv.z + bv.z;
        o.w = v[j].w * rstd * gv.w + bv.w;
        *(float4*)&out[row * DM + c] = o;
        *(uint2*)&oh[row * DM + c] = make_uint2(pack_h2(o.x, o.y), pack_h2(o.z, o.w));
    }
}

// ---------------------------------------------------------------------------
// pool / head
// ---------------------------------------------------------------------------
__device__ __forceinline__ float block_sum(float v, float* red, int nwarps)
{
    int lane = threadIdx.x & 31, w = threadIdx.x >> 5;
#pragma unroll
    for (int off = 16; off > 0; off >>= 1)
        v += __shfl_xor_sync(0xffffffffu, v, off);
    if (lane == 0) red[w] = v;
    __syncthreads();
    if (w == 0) {
        float ts = (lane < nwarps) ? red[lane] : 0.0f;
#pragma unroll
        for (int off = 16; off > 0; off >>= 1)
            ts += __shfl_xor_sync(0xffffffffu, ts, off);
        if (lane == 0) red[0] = ts;
    }
    __syncthreads();
    float r = red[0];
    __syncthreads();
    return r;
}

__global__ __launch_bounds__(512)
void pool_kernel(const float* __restrict__ h, float* __restrict__ pooled)
{
    int b = blockIdx.x, d = threadIdx.x;
    const float* p = h + (size_t)b * S_ * DM + d;
    float s = 0.0f;
#pragma unroll 8
    for (int i = 0; i < S_; i++) s += p[(size_t)i * DM];
    pooled[b * DM + d] = s * (1.0f / S_);
}

__global__ __launch_bounds__(512)
void final_kernel(const float* __restrict__ pooled, const float* __restrict__ lng,
                  const float* __restrict__ lnb, const float* __restrict__ fcw,
                  const float* __restrict__ fcb, float* __restrict__ out)
{
    __shared__ float red[32];
    int b = blockIdx.x, d = threadIdx.x;
    float x = pooled[b * DM + d];
    float mu = block_sum(x, red, 16) * (1.0f / DM);
    float dx = x - mu;
    float var = block_sum(dx * dx, red, 16) * (1.0f / DM);
    float y = dx * rsqrtf(var + 1e-5f) * lng[d] + lnb[d];
    float z = block_sum(y * fcw[d], red, 16);
    if (d == 0) out[b] = 1.0f / (1.0f + expf(-(z + fcb[0])));
}

// ---------------------------------------------------------------------------
// launch
// ---------------------------------------------------------------------------
extern "C" void kernel_launch(void* const* d_in, const int* in_sizes, int n_in,
                              void* d_out, int out_size)
{
    const float* x    = (const float*)d_in[0];
    const float* Wp   = (const float*)d_in[1];
    const float* bp   = (const float*)d_in[2];
    const float* Wq   = (const float*)d_in[3];
    const float* bq   = (const float*)d_in[4];
    const float* Wk   = (const float*)d_in[5];
    const float* bk   = (const float*)d_in[6];
    const float* Wv   = (const float*)d_in[7];
    const float* bv   = (const float*)d_in[8];
    const float* Wo   = (const float*)d_in[9];
    const float* bo   = (const float*)d_in[10];
    const float* ln1g = (const float*)d_in[11];
    const float* ln1b = (const float*)d_in[12];
    const float* W1   = (const float*)d_in[13];
    const float* b1   = (const float*)d_in[14];
    const float* W2   = (const float*)d_in[15];
    const float* b2   = (const float*)d_in[16];
    const float* ln2g = (const float*)d_in[17];
    const float* ln2b = (const float*)d_in[18];
    const float* lng  = (const float*)d_in[19];
    const float* lnb  = (const float*)d_in[20];
    const float* fcw  = (const float*)d_in[21];
    const float* fcb  = (const float*)d_in[22];
    float* out = (float*)d_out;

    float *h, *tmp, *pooled, *bqkv;
    __half *x16, *h16, *c16, *q16, *k16, *v16, *w16;
    cudaGetSymbolAddress((void**)&h, g_h);
    cudaGetSymbolAddress((void**)&tmp, g_tmp);
    cudaGetSymbolAddress((void**)&pooled, g_pool);
    cudaGetSymbolAddress((void**)&bqkv, g_bqkv);
    cudaGetSymbolAddress((void**)&x16, g_x16);
    cudaGetSymbolAddress((void**)&h16, g_h16);
    cudaGetSymbolAddress((void**)&c16, g_c16);
    cudaGetSymbolAddress((void**)&q16, g_q16);
    cudaGetSymbolAddress((void**)&k16, g_k16);
    cudaGetSymbolAddress((void**)&v16, g_v16);
    cudaGetSymbolAddress((void**)&w16, g_w16);

    cudaFuncSetAttribute(gemm_mma<2,true,true>,  cudaFuncAttributeMaxDynamicSharedMemorySize, GSMEM_TOTAL);
    cudaFuncSetAttribute(gemm_mma<4,true,false>, cudaFuncAttributeMaxDynamicSharedMemorySize, GSMEM_TOTAL);
    cudaFuncSetAttribute(gemm_mma<3,false,true>, cudaFuncAttributeMaxDynamicSharedMemorySize, GSMEM_TOTAL);
    cudaFuncSetAttribute(gemm_mma<1,true,false>, cudaFuncAttributeMaxDynamicSharedMemorySize, GSMEM_TOTAL);
    cudaFuncSetAttribute(attn_mma, cudaFuncAttributeMaxDynamicSharedMemorySize, ATTN_SMEM);

    // ---- preprocessing: 4 launches ----
    wsplit_qkvo<<<dim3(16,16,17), 256>>>(Wq, Wk, Wv, Wo, w16+LBASE, bq, bk, bv, bqkv);
    wsplit_t<<<dim3(16,64,1), 256>>>(Wp, w16, FEAT, DM, 0, 0);
    wsplit_t<<<dim3(64,16,NL), 256>>>(W1, w16+LBASE+1048576, DM, DFF,
                                      (size_t)DM*DFF, LSTRIDE);
    wsplit_w2x<<<dim3(16,64,36), 256>>>(W2, w16+LBASE+2097152, x, x16);

    dim3 gDM(DM / 128, NTOK / 128);
    dim3 gQKV(1536 / 128, NTOK / 128);
    dim3 gFF(DFF / 128, NTOK / 128);
    dim3 gAtt(S_ / 128, B_ * NH);

    gemm_mma<2,true,true><<<gDM, 256, GSMEM_TOTAL>>>(
        x16, w16, bp, nullptr, h, h16, nullptr, nullptr, DM, FEAT);

    for (int l = 0; l < NL; l++) {
        size_t b0 = LBASE + (size_t)l * LSTRIDE;
        gemm_mma<4,true,false><<<gQKV, 256, GSMEM_TOTAL>>>(
            h16, w16+b0, bqkv + l*1536, nullptr, nullptr,
            q16, k16, v16, DM, DM);

        attn_mma<<<gAtt, 256, ATTN_SMEM>>>(q16, k16, v16, c16);

        gemm_mma<3,false,true><<<gDM, 256, GSMEM_TOTAL>>>(
            c16, w16+b0+786432, bo + l*DM, h, tmp, nullptr, nullptr, nullptr, DM, DM);
        ln_kernel<<<NTOK/8, 256>>>(tmp, ln1g + l*DM, ln1b + l*DM, h, h16);

        gemm_mma<1,true,false><<<gFF, 256, GSMEM_TOTAL>>>(
            h16, w16+b0+1048576, b1 + l*DFF, nullptr, nullptr,
            x16, nullptr, nullptr, DFF, DM);
        gemm_mma<3,false,true><<<gDM, 256, GSMEM_TOTAL>>>(
            x16, w16+b0+2097152, b2 + l*DM, h, tmp, nullptr, nullptr, nullptr, DM, DFF);
        ln_kernel<<<NTOK/8, 256>>>(tmp, ln2g + l*DM, ln2b + l*DM, h, h16);
    }

    pool_kernel<<<B_, 512>>>(h, pooled);
    final_kernel<<<B_, 512>>>(pooled, lng, lnb, fcw, fcb, out);
}